// round 1
// baseline (speedup 1.0000x reference)
#include <cuda_runtime.h>
#include <cuda_bf16.h>
#include <math.h>

#define DIM 2048
#define T_LEN 2048
#define NHEAD 16
#define HDIM 128
#define ATTN_SCALE 0.12f
#define NEG_INF (-1.0f/0.0f)

// ---------------- scratch ----------------
__device__ float g_qkv[T_LEN * 3 * DIM];        // [t][e*2048 + h*128 + d]
__device__ float g_q[NHEAD * T_LEN * HDIM];     // [h][t][d]
__device__ float g_k[NHEAD * T_LEN * HDIM];
__device__ float g_v[NHEAD * T_LEN * HDIM];
__device__ float g_y[T_LEN * DIM];              // [t][h*128+d]

// ---------------- NT SGEMM: C[M,N] = A[M,K] * B[N,K]^T ----------------
// A row-major MxK, B row-major NxK, C row-major MxN. M,N % 128 == 0, K % 16 == 0.
__global__ __launch_bounds__(256) void sgemm_nt(
    const float* __restrict__ A, const float* __restrict__ B,
    float* __restrict__ C, int M, int N, int K)
{
    __shared__ float As[16][132];
    __shared__ float Bs[16][132];
    int tid = threadIdx.x;
    int tx = tid & 15, ty = tid >> 4;
    int m0 = blockIdx.y * 128, n0 = blockIdx.x * 128;
    int row = tid >> 1;            // 0..127
    int kc  = (tid & 1) * 8;       // 0 or 8
    const float* Ag = A + (size_t)(m0 + row) * K + kc;
    const float* Bg = B + (size_t)(n0 + row) * K + kc;

    float acc[8][8];
    #pragma unroll
    for (int i = 0; i < 8; i++)
        #pragma unroll
        for (int j = 0; j < 8; j++) acc[i][j] = 0.0f;

    for (int k0 = 0; k0 < K; k0 += 16) {
        float4 a0 = *(const float4*)(Ag + k0);
        float4 a1 = *(const float4*)(Ag + k0 + 4);
        float4 b0 = *(const float4*)(Bg + k0);
        float4 b1 = *(const float4*)(Bg + k0 + 4);
        __syncthreads();
        As[kc+0][row]=a0.x; As[kc+1][row]=a0.y; As[kc+2][row]=a0.z; As[kc+3][row]=a0.w;
        As[kc+4][row]=a1.x; As[kc+5][row]=a1.y; As[kc+6][row]=a1.z; As[kc+7][row]=a1.w;
        Bs[kc+0][row]=b0.x; Bs[kc+1][row]=b0.y; Bs[kc+2][row]=b0.z; Bs[kc+3][row]=b0.w;
        Bs[kc+4][row]=b1.x; Bs[kc+5][row]=b1.y; Bs[kc+6][row]=b1.z; Bs[kc+7][row]=b1.w;
        __syncthreads();
        #pragma unroll
        for (int kk = 0; kk < 16; kk++) {
            float4 av0 = *(const float4*)&As[kk][ty*8];
            float4 av1 = *(const float4*)&As[kk][ty*8+4];
            float4 bv0 = *(const float4*)&Bs[kk][tx*8];
            float4 bv1 = *(const float4*)&Bs[kk][tx*8+4];
            float a[8] = {av0.x,av0.y,av0.z,av0.w,av1.x,av1.y,av1.z,av1.w};
            float b[8] = {bv0.x,bv0.y,bv0.z,bv0.w,bv1.x,bv1.y,bv1.z,bv1.w};
            #pragma unroll
            for (int i = 0; i < 8; i++)
                #pragma unroll
                for (int j = 0; j < 8; j++)
                    acc[i][j] = fmaf(a[i], b[j], acc[i][j]);
        }
    }
    #pragma unroll
    for (int i = 0; i < 8; i++) {
        float4 o0 = make_float4(acc[i][0],acc[i][1],acc[i][2],acc[i][3]);
        float4 o1 = make_float4(acc[i][4],acc[i][5],acc[i][6],acc[i][7]);
        float* cp = C + (size_t)(m0 + ty*8 + i) * N + n0 + tx*8;
        *(float4*)cp = o0;
        *(float4*)(cp + 4) = o1;
    }
}

// ---------------- RMSNorm + RoPE + v-mix ----------------
__global__ __launch_bounds__(128) void fuse_kernel(
    const float* __restrict__ qkv, const float* __restrict__ ve,
    const float* __restrict__ lambdas,
    float* __restrict__ Qo, float* __restrict__ Ko, float* __restrict__ Vo)
{
    int t = blockIdx.x, h = blockIdx.y, d = threadIdx.x;
    size_t base = (size_t)t * (3*DIM) + h * HDIM + d;
    float q = qkv[base];
    float k = qkv[base + DIM];
    float v = qkv[base + 2*DIM];

    __shared__ float red[3][4];
    __shared__ float qn_s[128], kn_s[128];
    float sq = q*q, sk = k*k, sv = v*v;
    #pragma unroll
    for (int off = 16; off > 0; off >>= 1) {
        sq += __shfl_xor_sync(0xffffffffu, sq, off);
        sk += __shfl_xor_sync(0xffffffffu, sk, off);
        sv += __shfl_xor_sync(0xffffffffu, sv, off);
    }
    int warp = d >> 5, lane = d & 31;
    if (lane == 0) { red[0][warp] = sq; red[1][warp] = sk; red[2][warp] = sv; }
    __syncthreads();
    sq = red[0][0]+red[0][1]+red[0][2]+red[0][3];
    sk = red[1][0]+red[1][1]+red[1][2]+red[1][3];
    sv = red[2][0]+red[2][1]+red[2][2]+red[2][3];
    float rq = rsqrtf(sq * (1.0f/128.0f) + 1e-6f);
    float rk = rsqrtf(sk * (1.0f/128.0f) + 1e-6f);
    float rv = rsqrtf(sv * (1.0f/128.0f) + 1e-6f);
    float qn = q * rq, kn = k * rk, vn = v * rv;
    qn_s[d] = qn; kn_s[d] = kn;
    __syncthreads();

    // rope: freq index j = d%64, freq = j<32 ? 1024^{-j/31} : 0
    int j = (d < 64) ? d : (d - 64);
    float f = (j < 32) ? exp2f(-10.0f * (float)j / 31.0f) : 0.0f;
    float th = (float)t * f;
    float sn, cs;
    sincosf(th, &sn, &cs);
    float oq, ok;
    if (d < 64) {
        oq =  qn * cs + qn_s[d+64] * sn;
        ok =  kn * cs + kn_s[d+64] * sn;
    } else {
        oq = -qn_s[d-64] * sn + qn * cs;
        ok = -kn_s[d-64] * sn + kn * cs;
    }
    float l0 = lambdas[0], l1 = lambdas[1];
    float vm = l0 * vn + l1 * ve[(size_t)t * DIM + h * HDIM + d];

    size_t oidx = ((size_t)h * T_LEN + t) * HDIM + d;
    Qo[oidx] = oq; Ko[oidx] = ok; Vo[oidx] = vm;
}

// ---------------- causal flash attention (fp32) ----------------
// Q,K,V: [H][T][128]. Y: [T][H*128]. Block = (qt, h), 256 threads, BQ=BK=64.
__global__ __launch_bounds__(256) void attn_kernel(
    const float* __restrict__ Q, const float* __restrict__ K,
    const float* __restrict__ V, float* __restrict__ Y)
{
    extern __shared__ float sm[];
    float* Qs  = sm;            // 64*128
    float* Kst = Qs + 8192;     // [128][68] d-major
    float* Vs  = Kst + 8704;    // 64*128
    float* Ps  = Vs + 8192;     // [64][68]

    int tid = threadIdx.x;
    int tx = tid & 15, ty = tid >> 4;
    int qt = blockIdx.x, h = blockIdx.y;
    int q0 = qt * 64;

    const float4* Qg = (const float4*)(Q + ((size_t)h * T_LEN + q0) * HDIM);
    float4* Qs4 = (float4*)Qs;
    #pragma unroll
    for (int l = tid; l < 2048; l += 256) Qs4[l] = Qg[l];

    float m[4], lsum[4], o[4][8];
    #pragma unroll
    for (int i = 0; i < 4; i++) {
        m[i] = NEG_INF; lsum[i] = 0.0f;
        #pragma unroll
        for (int c = 0; c < 8; c++) o[i][c] = 0.0f;
    }

    for (int kt = 0; kt <= qt; kt++) {
        const float4* Kg = (const float4*)(K + ((size_t)h * T_LEN + kt*64) * HDIM);
        const float4* Vg = (const float4*)(V + ((size_t)h * T_LEN + kt*64) * HDIM);
        __syncthreads();
        #pragma unroll
        for (int l = tid; l < 2048; l += 256) {
            float4 kv = Kg[l];
            int c  = l >> 5;          // key row in tile
            int dd = (l & 31) * 4;    // d offset
            Kst[(dd+0)*68 + c] = kv.x;
            Kst[(dd+1)*68 + c] = kv.y;
            Kst[(dd+2)*68 + c] = kv.z;
            Kst[(dd+3)*68 + c] = kv.w;
            ((float4*)Vs)[l] = Vg[l];
        }
        __syncthreads();

        float s[4][4];
        #pragma unroll
        for (int i = 0; i < 4; i++)
            #pragma unroll
            for (int jj = 0; jj < 4; jj++) s[i][jj] = 0.0f;

        #pragma unroll 4
        for (int d = 0; d < 128; d++) {
            float4 kv = *(const float4*)&Kst[d*68 + tx*4];
            float qv0 = Qs[(ty*4+0)*128 + d];
            float qv1 = Qs[(ty*4+1)*128 + d];
            float qv2 = Qs[(ty*4+2)*128 + d];
            float qv3 = Qs[(ty*4+3)*128 + d];
            s[0][0] = fmaf(qv0, kv.x, s[0][0]); s[0][1] = fmaf(qv0, kv.y, s[0][1]);
            s[0][2] = fmaf(qv0, kv.z, s[0][2]); s[0][3] = fmaf(qv0, kv.w, s[0][3]);
            s[1][0] = fmaf(qv1, kv.x, s[1][0]); s[1][1] = fmaf(qv1, kv.y, s[1][1]);
            s[1][2] = fmaf(qv1, kv.z, s[1][2]); s[1][3] = fmaf(qv1, kv.w, s[1][3]);
            s[2][0] = fmaf(qv2, kv.x, s[2][0]); s[2][1] = fmaf(qv2, kv.y, s[2][1]);
            s[2][2] = fmaf(qv2, kv.z, s[2][2]); s[2][3] = fmaf(qv2, kv.w, s[2][3]);
            s[3][0] = fmaf(qv3, kv.x, s[3][0]); s[3][1] = fmaf(qv3, kv.y, s[3][1]);
            s[3][2] = fmaf(qv3, kv.z, s[3][2]); s[3][3] = fmaf(qv3, kv.w, s[3][3]);
        }

        bool diag = (kt == qt);
        #pragma unroll
        for (int i = 0; i < 4; i++)
            #pragma unroll
            for (int jj = 0; jj < 4; jj++) {
                float v = s[i][jj] * ATTN_SCALE;
                if (diag && (tx*4 + jj) > (ty*4 + i)) v = NEG_INF;
                s[i][jj] = v;
            }

        #pragma unroll
        for (int i = 0; i < 4; i++) {
            float rm = fmaxf(fmaxf(s[i][0], s[i][1]), fmaxf(s[i][2], s[i][3]));
            #pragma unroll
            for (int off = 8; off > 0; off >>= 1)
                rm = fmaxf(rm, __shfl_xor_sync(0xffffffffu, rm, off, 16));
            float mnew = fmaxf(m[i], rm);
            float alpha = __expf(m[i] - mnew);
            float rs = 0.0f;
            #pragma unroll
            for (int jj = 0; jj < 4; jj++) {
                float p = __expf(s[i][jj] - mnew);
                Ps[(ty*4+i)*68 + tx*4 + jj] = p;
                rs += p;
            }
            #pragma unroll
            for (int off = 8; off > 0; off >>= 1)
                rs += __shfl_xor_sync(0xffffffffu, rs, off, 16);
            lsum[i] = lsum[i] * alpha + rs;
            m[i] = mnew;
            #pragma unroll
            for (int c = 0; c < 8; c++) o[i][c] *= alpha;
        }
        __syncthreads();

        #pragma unroll 2
        for (int jj = 0; jj < 64; jj++) {
            float4 va = *(const float4*)&Vs[jj*128 + tx*8];
            float4 vb = *(const float4*)&Vs[jj*128 + tx*8 + 4];
            #pragma unroll
            for (int i = 0; i < 4; i++) {
                float p = Ps[(ty*4+i)*68 + jj];
                o[i][0] = fmaf(p, va.x, o[i][0]); o[i][1] = fmaf(p, va.y, o[i][1]);
                o[i][2] = fmaf(p, va.z, o[i][2]); o[i][3] = fmaf(p, va.w, o[i][3]);
                o[i][4] = fmaf(p, vb.x, o[i][4]); o[i][5] = fmaf(p, vb.y, o[i][5]);
                o[i][6] = fmaf(p, vb.z, o[i][6]); o[i][7] = fmaf(p, vb.w, o[i][7]);
            }
        }
    }

    #pragma unroll
    for (int i = 0; i < 4; i++) {
        float inv = 1.0f / lsum[i];
        int row = q0 + ty*4 + i;
        float4 r0 = make_float4(o[i][0]*inv, o[i][1]*inv, o[i][2]*inv, o[i][3]*inv);
        float4 r1 = make_float4(o[i][4]*inv, o[i][5]*inv, o[i][6]*inv, o[i][7]*inv);
        float* yp = Y + (size_t)row * DIM + h * HDIM + tx*8;
        *(float4*)yp = r0;
        *(float4*)(yp + 4) = r1;
    }
}

// ---------------- launch ----------------
extern "C" void kernel_launch(void* const* d_in, const int* in_sizes, int n_in,
                              void* d_out, int out_size)
{
    const float* x       = (const float*)d_in[0];
    const float* w       = (const float*)d_in[1];   // [4,2048,2048]
    const float* ve      = (const float*)d_in[2];
    const float* lambdas = (const float*)d_in[3];
    float* out = (float*)d_out;

    float *p_qkv, *p_q, *p_k, *p_v, *p_y;
    cudaGetSymbolAddress((void**)&p_qkv, g_qkv);
    cudaGetSymbolAddress((void**)&p_q,   g_q);
    cudaGetSymbolAddress((void**)&p_k,   g_k);
    cudaGetSymbolAddress((void**)&p_v,   g_v);
    cudaGetSymbolAddress((void**)&p_y,   g_y);

    static const int ATTN_SMEM = (8192 + 8704 + 8192 + 4352) * 4;  // 117760 B
    cudaFuncSetAttribute(attn_kernel, cudaFuncAttributeMaxDynamicSharedMemorySize, ATTN_SMEM);

    // 1) qkv = x @ W_qkv^T : [2048, 6144]
    sgemm_nt<<<dim3(3*DIM/128, T_LEN/128), 256>>>(x, w, p_qkv, T_LEN, 3*DIM, DIM);
    // 2) rmsnorm + rope + v-mix
    fuse_kernel<<<dim3(T_LEN, NHEAD), 128>>>(p_qkv, ve, lambdas, p_q, p_k, p_v);
    // 3) causal attention
    attn_kernel<<<dim3(T_LEN/64, NHEAD), 256, ATTN_SMEM>>>(p_q, p_k, p_v, p_y);
    // 4) out = y @ W_o^T : [2048, 2048]
    sgemm_nt<<<dim3(DIM/128, T_LEN/128), 256>>>(p_y, w + (size_t)3*DIM*DIM, out, T_LEN, DIM, DIM);
}

// round 6
// speedup vs baseline: 1.6370x; 1.6370x over previous
#include <cuda_runtime.h>
#include <cuda_bf16.h>
#include <math.h>
#include <stdint.h>

#define DIM 2048
#define T_LEN 2048
#define NHEAD 16
#define HDIM 128
#define ATTN_SCALE 0.12f
#define NEG_INF (-1.0f/0.0f)

// ---------------- scratch ----------------
__device__ float g_qkv[T_LEN * 3 * DIM];        // [t][e*2048 + h*128 + d]
__device__ float g_q[NHEAD * T_LEN * HDIM];     // [h][t][d]
__device__ float g_k[NHEAD * T_LEN * HDIM];
__device__ float g_v[NHEAD * T_LEN * HDIM];
__device__ float g_y[T_LEN * DIM];              // [t][h*128+d]
__device__ __nv_bfloat16 g_whi[4 * DIM * DIM];
__device__ __nv_bfloat16 g_wlo[4 * DIM * DIM];
__device__ __nv_bfloat16 g_xhi[T_LEN * DIM];
__device__ __nv_bfloat16 g_xlo[T_LEN * DIM];
__device__ __nv_bfloat16 g_yhi[T_LEN * DIM];
__device__ __nv_bfloat16 g_ylo[T_LEN * DIM];

// ---------------- PTX helpers (portable: sm_80+ instructions only) ----------------
__device__ __forceinline__ uint32_t smem_to_u32(const void* p) {
    uint32_t a;
    asm("{ .reg .u64 t; cvta.to.shared.u64 t, %1; cvt.u32.u64 %0, t; }" : "=r"(a) : "l"(p));
    return a;
}
__device__ __forceinline__ void cp16(uint32_t dst, const void* src) {
    asm volatile("cp.async.cg.shared.global [%0], [%1], 16;" :: "r"(dst), "l"(src) : "memory");
}
__device__ __forceinline__ void ldsm4(uint32_t* r, uint32_t a) {
    asm volatile("ldmatrix.sync.aligned.m8n8.x4.shared.b16 {%0,%1,%2,%3}, [%4];"
        : "=r"(r[0]), "=r"(r[1]), "=r"(r[2]), "=r"(r[3]) : "r"(a));
}
__device__ __forceinline__ void ldsm2(uint32_t* r, uint32_t a) {
    asm volatile("ldmatrix.sync.aligned.m8n8.x2.shared.b16 {%0,%1}, [%2];"
        : "=r"(r[0]), "=r"(r[1]) : "r"(a));
}
__device__ __forceinline__ void mma16816(float* d, const uint32_t* a, const uint32_t* b) {
    asm volatile("mma.sync.aligned.m16n8k16.row.col.f32.bf16.bf16.f32 "
        "{%0,%1,%2,%3}, {%4,%5,%6,%7}, {%8,%9}, {%0,%1,%2,%3};"
        : "+f"(d[0]), "+f"(d[1]), "+f"(d[2]), "+f"(d[3])
        : "r"(a[0]), "r"(a[1]), "r"(a[2]), "r"(a[3]), "r"(b[0]), "r"(b[1]));
}

// ---------------- fp32 -> bf16 hi/lo split ----------------
__global__ __launch_bounds__(256) void split_kernel(
    const float4* __restrict__ src, uint2* __restrict__ hi, uint2* __restrict__ lo, int n4)
{
    int i = blockIdx.x * 256 + threadIdx.x;
    if (i >= n4) return;
    float4 v = src[i];
    float a[4] = {v.x, v.y, v.z, v.w};
    uint32_t hb[4], lb[4];
    #pragma unroll
    for (int u = 0; u < 4; u++) {
        __nv_bfloat16 h = __float2bfloat16(a[u]);
        float l = a[u] - __bfloat162float(h);
        __nv_bfloat16 lo16 = __float2bfloat16(l);
        hb[u] = (uint32_t)__bfloat16_as_ushort(h);
        lb[u] = (uint32_t)__bfloat16_as_ushort(lo16);
    }
    uint2 H, L;
    H.x = hb[0] | (hb[1] << 16); H.y = hb[2] | (hb[3] << 16);
    L.x = lb[0] | (lb[1] << 16); L.y = lb[2] | (lb[3] << 16);
    hi[i] = H; lo[i] = L;
}

// ---------------- bf16x3 HMMA GEMM: C[M,N] = A[M,K] * B[N,K]^T ----------------
// CTA tile 128x128, 8 warps (64x32 warp tiles), K-chunk 32, cp.async double buffer.
// Smem rows padded to 40 bf16 (80B) for conflict-free ldmatrix.
#define GKC 32
#define ROWB 80            // bytes per padded row (40 bf16)
#define ARR_BYTES (128 * ROWB)   // 10240
#define AHI_OFF 0
#define ALO_OFF 10240
#define BHI_OFF 20480
#define BLO_OFF 30720
#define STAGE_BYTES 40960
#define GEMM_SMEM (2 * STAGE_BYTES)

__global__ __launch_bounds__(256, 1) void gemm_bf16x3(
    const __nv_bfloat16* __restrict__ Ahi, const __nv_bfloat16* __restrict__ Alo,
    const __nv_bfloat16* __restrict__ Bhi, const __nv_bfloat16* __restrict__ Blo,
    float* __restrict__ C, int M, int N, int K)
{
    extern __shared__ char smc[];
    uint32_t smem_base = smem_to_u32(smc);
    int tid = threadIdx.x, wid = tid >> 5, lane = tid & 31;
    int m0 = blockIdx.y * 128, n0 = blockIdx.x * 128;
    int wy = wid & 1, wx = wid >> 1;           // warp tile: rows wy*64, cols wx*32
    int mb = wy * 64, nb = wx * 32;

    // per-lane ldmatrix address components
    uint32_t arow = (uint32_t)((lane & 15) * ROWB + ((lane >> 4) & 1) * 16);
    uint32_t brow = (uint32_t)((lane & 7) * ROWB + ((lane >> 3) & 1) * 16);

    float acc[4][4][4];
    #pragma unroll
    for (int i = 0; i < 4; i++)
        #pragma unroll
        for (int j = 0; j < 4; j++)
            #pragma unroll
            for (int u = 0; u < 4; u++) acc[i][j][u] = 0.0f;

    auto fill_async = [&](int s, int k0) {
        uint32_t sb = smem_base + s * STAGE_BYTES;
        #pragma unroll
        for (int rep = 0; rep < 2; rep++) {
            int i = tid + rep * 256;          // 0..511
            int row = i >> 2, seg = i & 3;
            uint32_t doff = (uint32_t)(row * ROWB + seg * 16);
            size_t ga = (size_t)(m0 + row) * K + k0 + seg * 8;
            size_t gb = (size_t)(n0 + row) * K + k0 + seg * 8;
            cp16(sb + AHI_OFF + doff, Ahi + ga);
            cp16(sb + ALO_OFF + doff, Alo + ga);
            cp16(sb + BHI_OFF + doff, Bhi + gb);
            cp16(sb + BLO_OFF + doff, Blo + gb);
        }
    };

    const int nchunks = K / GKC;

    // prologue: load chunk 0
    fill_async(0, 0);
    asm volatile("cp.async.commit_group;" ::: "memory");
    asm volatile("cp.async.wait_group 0;" ::: "memory");
    __syncthreads();

    for (int c = 0; c < nchunks; c++) {
        if (c + 1 < nchunks) fill_async((c + 1) & 1, (c + 1) * GKC);
        asm volatile("cp.async.commit_group;" ::: "memory");

        uint32_t sb = smem_base + (c & 1) * STAGE_BYTES;
        #pragma unroll
        for (int ks = 0; ks < 2; ks++) {
            uint32_t ah[4][4], al[4][4], bh[4][2], bl[4][2];
            #pragma unroll
            for (int mi = 0; mi < 4; mi++) {
                uint32_t base = sb + (uint32_t)((mb + mi * 16) * ROWB + ks * 32) + arow;
                ldsm4(ah[mi], base + AHI_OFF);
                ldsm4(al[mi], base + ALO_OFF);
            }
            #pragma unroll
            for (int ni = 0; ni < 4; ni++) {
                uint32_t base = sb + (uint32_t)((nb + ni * 8) * ROWB + ks * 32) + brow;
                ldsm2(bh[ni], base + BHI_OFF);
                ldsm2(bl[ni], base + BLO_OFF);
            }
            #pragma unroll
            for (int mi = 0; mi < 4; mi++)
                #pragma unroll
                for (int ni = 0; ni < 4; ni++) {
                    mma16816(acc[mi][ni], ah[mi], bh[ni]);
                    mma16816(acc[mi][ni], ah[mi], bl[ni]);
                    mma16816(acc[mi][ni], al[mi], bh[ni]);
                }
        }
        asm volatile("cp.async.wait_group 0;" ::: "memory");
        __syncthreads();
    }

    // epilogue: fp32 accum -> C
    int r0 = lane >> 2, c2 = (lane & 3) * 2;
    #pragma unroll
    for (int mi = 0; mi < 4; mi++) {
        int rowa = m0 + mb + mi * 16 + r0;
        #pragma unroll
        for (int ni = 0; ni < 4; ni++) {
            int col = n0 + nb + ni * 8 + c2;
            float2 v0 = make_float2(acc[mi][ni][0], acc[mi][ni][1]);
            float2 v1 = make_float2(acc[mi][ni][2], acc[mi][ni][3]);
            *(float2*)(C + (size_t)rowa * N + col) = v0;
            *(float2*)(C + (size_t)(rowa + 8) * N + col) = v1;
        }
    }
}

// ---------------- RMSNorm + RoPE + v-mix ----------------
__global__ __launch_bounds__(128) void fuse_kernel(
    const float* __restrict__ qkv, const float* __restrict__ ve,
    const float* __restrict__ lambdas,
    float* __restrict__ Qo, float* __restrict__ Ko, float* __restrict__ Vo)
{
    int t = blockIdx.x, h = blockIdx.y, d = threadIdx.x;
    size_t base = (size_t)t * (3*DIM) + h * HDIM + d;
    float q = qkv[base];
    float k = qkv[base + DIM];
    float v = qkv[base + 2*DIM];

    __shared__ float red[3][4];
    __shared__ float qn_s[128], kn_s[128];
    float sq = q*q, sk = k*k, sv = v*v;
    #pragma unroll
    for (int off = 16; off > 0; off >>= 1) {
        sq += __shfl_xor_sync(0xffffffffu, sq, off);
        sk += __shfl_xor_sync(0xffffffffu, sk, off);
        sv += __shfl_xor_sync(0xffffffffu, sv, off);
    }
    int warp = d >> 5, lane = d & 31;
    if (lane == 0) { red[0][warp] = sq; red[1][warp] = sk; red[2][warp] = sv; }
    __syncthreads();
    sq = red[0][0]+red[0][1]+red[0][2]+red[0][3];
    sk = red[1][0]+red[1][1]+red[1][2]+red[1][3];
    sv = red[2][0]+red[2][1]+red[2][2]+red[2][3];
    float rq = rsqrtf(sq * (1.0f/128.0f) + 1e-6f);
    float rk = rsqrtf(sk * (1.0f/128.0f) + 1e-6f);
    float rv = rsqrtf(sv * (1.0f/128.0f) + 1e-6f);
    float qn = q * rq, kn = k * rk, vn = v * rv;
    qn_s[d] = qn; kn_s[d] = kn;
    __syncthreads();

    int j = (d < 64) ? d : (d - 64);
    float f = (j < 32) ? exp2f(-10.0f * (float)j / 31.0f) : 0.0f;
    float th = (float)t * f;
    float sn, cs;
    sincosf(th, &sn, &cs);
    float oq, ok;
    if (d < 64) {
        oq =  qn * cs + qn_s[d+64] * sn;
        ok =  kn * cs + kn_s[d+64] * sn;
    } else {
        oq = -qn_s[d-64] * sn + qn * cs;
        ok = -kn_s[d-64] * sn + kn * cs;
    }
    float l0 = lambdas[0], l1 = lambdas[1];
    float vm = l0 * vn + l1 * ve[(size_t)t * DIM + h * HDIM + d];

    size_t oidx = ((size_t)h * T_LEN + t) * HDIM + d;
    Qo[oidx] = oq; Ko[oidx] = ok; Vo[oidx] = vm;
}

// ---------------- causal flash attention (fp32) ----------------
__global__ __launch_bounds__(256) void attn_kernel(
    const float* __restrict__ Q, const float* __restrict__ K,
    const float* __restrict__ V, float* __restrict__ Y)
{
    extern __shared__ float sm[];
    float* Qs  = sm;            // 64*128
    float* Kst = Qs + 8192;     // [128][68] d-major
    float* Vs  = Kst + 8704;    // 64*128
    float* Ps  = Vs + 8192;     // [64][68]

    int tid = threadIdx.x;
    int tx = tid & 15, ty = tid >> 4;
    int qt = blockIdx.x, h = blockIdx.y;
    int q0 = qt * 64;

    const float4* Qg = (const float4*)(Q + ((size_t)h * T_LEN + q0) * HDIM);
    float4* Qs4 = (float4*)Qs;
    #pragma unroll
    for (int l = tid; l < 2048; l += 256) Qs4[l] = Qg[l];

    float m[4], lsum[4], o[4][8];
    #pragma unroll
    for (int i = 0; i < 4; i++) {
        m[i] = NEG_INF; lsum[i] = 0.0f;
        #pragma unroll
        for (int c = 0; c < 8; c++) o[i][c] = 0.0f;
    }

    for (int kt = 0; kt <= qt; kt++) {
        const float4* Kg = (const float4*)(K + ((size_t)h * T_LEN + kt*64) * HDIM);
        const float4* Vg = (const float4*)(V + ((size_t)h * T_LEN + kt*64) * HDIM);
        __syncthreads();
        #pragma unroll
        for (int l = tid; l < 2048; l += 256) {
            float4 kv = Kg[l];
            int c  = l >> 5;
            int dd = (l & 31) * 4;
            Kst[(dd+0)*68 + c] = kv.x;
            Kst[(dd+1)*68 + c] = kv.y;
            Kst[(dd+2)*68 + c] = kv.z;
            Kst[(dd+3)*68 + c] = kv.w;
            ((float4*)Vs)[l] = Vg[l];
        }
        __syncthreads();

        float s[4][4];
        #pragma unroll
        for (int i = 0; i < 4; i++)
            #pragma unroll
            for (int jj = 0; jj < 4; jj++) s[i][jj] = 0.0f;

        #pragma unroll 4
        for (int d = 0; d < 128; d++) {
            float4 kv = *(const float4*)&Kst[d*68 + tx*4];
            float qv0 = Qs[(ty*4+0)*128 + d];
            float qv1 = Qs[(ty*4+1)*128 + d];
            float qv2 = Qs[(ty*4+2)*128 + d];
            float qv3 = Qs[(ty*4+3)*128 + d];
            s[0][0] = fmaf(qv0, kv.x, s[0][0]); s[0][1] = fmaf(qv0, kv.y, s[0][1]);
            s[0][2] = fmaf(qv0, kv.z, s[0][2]); s[0][3] = fmaf(qv0, kv.w, s[0][3]);
            s[1][0] = fmaf(qv1, kv.x, s[1][0]); s[1][1] = fmaf(qv1, kv.y, s[1][1]);
            s[1][2] = fmaf(qv1, kv.z, s[1][2]); s[1][3] = fmaf(qv1, kv.w, s[1][3]);
            s[2][0] = fmaf(qv2, kv.x, s[2][0]); s[2][1] = fmaf(qv2, kv.y, s[2][1]);
            s[2][2] = fmaf(qv2, kv.z, s[2][2]); s[2][3] = fmaf(qv2, kv.w, s[2][3]);
            s[3][0] = fmaf(qv3, kv.x, s[3][0]); s[3][1] = fmaf(qv3, kv.y, s[3][1]);
            s[3][2] = fmaf(qv3, kv.z, s[3][2]); s[3][3] = fmaf(qv3, kv.w, s[3][3]);
        }

        bool diag = (kt == qt);
        #pragma unroll
        for (int i = 0; i < 4; i++)
            #pragma unroll
            for (int jj = 0; jj < 4; jj++) {
                float v = s[i][jj] * ATTN_SCALE;
                if (diag && (tx*4 + jj) > (ty*4 + i)) v = NEG_INF;
                s[i][jj] = v;
            }

        #pragma unroll
        for (int i = 0; i < 4; i++) {
            float rm = fmaxf(fmaxf(s[i][0], s[i][1]), fmaxf(s[i][2], s[i][3]));
            #pragma unroll
            for (int off = 8; off > 0; off >>= 1)
                rm = fmaxf(rm, __shfl_xor_sync(0xffffffffu, rm, off, 16));
            float mnew = fmaxf(m[i], rm);
            float alpha = __expf(m[i] - mnew);
            float rs = 0.0f;
            #pragma unroll
            for (int jj = 0; jj < 4; jj++) {
                float p = __expf(s[i][jj] - mnew);
                Ps[(ty*4+i)*68 + tx*4 + jj] = p;
                rs += p;
            }
            #pragma unroll
            for (int off = 8; off > 0; off >>= 1)
                rs += __shfl_xor_sync(0xffffffffu, rs, off, 16);
            lsum[i] = lsum[i] * alpha + rs;
            m[i] = mnew;
            #pragma unroll
            for (int c = 0; c < 8; c++) o[i][c] *= alpha;
        }
        __syncthreads();

        #pragma unroll 2
        for (int jj = 0; jj < 64; jj++) {
            float4 va = *(const float4*)&Vs[jj*128 + tx*8];
            float4 vb = *(const float4*)&Vs[jj*128 + tx*8 + 4];
            #pragma unroll
            for (int i = 0; i < 4; i++) {
                float p = Ps[(ty*4+i)*68 + jj];
                o[i][0] = fmaf(p, va.x, o[i][0]); o[i][1] = fmaf(p, va.y, o[i][1]);
                o[i][2] = fmaf(p, va.z, o[i][2]); o[i][3] = fmaf(p, va.w, o[i][3]);
                o[i][4] = fmaf(p, vb.x, o[i][4]); o[i][5] = fmaf(p, vb.y, o[i][5]);
                o[i][6] = fmaf(p, vb.z, o[i][6]); o[i][7] = fmaf(p, vb.w, o[i][7]);
            }
        }
    }

    #pragma unroll
    for (int i = 0; i < 4; i++) {
        float inv = 1.0f / lsum[i];
        int row = q0 + ty*4 + i;
        float4 r0 = make_float4(o[i][0]*inv, o[i][1]*inv, o[i][2]*inv, o[i][3]*inv);
        float4 r1 = make_float4(o[i][4]*inv, o[i][5]*inv, o[i][6]*inv, o[i][7]*inv);
        float* yp = Y + (size_t)row * DIM + h * HDIM + tx*8;
        *(float4*)yp = r0;
        *(float4*)(yp + 4) = r1;
    }
}

// ---------------- launch ----------------
extern "C" void kernel_launch(void* const* d_in, const int* in_sizes, int n_in,
                              void* d_out, int out_size)
{
    const float* x       = (const float*)d_in[0];
    const float* w       = (const float*)d_in[1];   // [4,2048,2048]
    const float* ve      = (const float*)d_in[2];
    const float* lambdas = (const float*)d_in[3];
    float* out = (float*)d_out;

    float *p_qkv, *p_q, *p_k, *p_v, *p_y;
    __nv_bfloat16 *p_whi, *p_wlo, *p_xhi, *p_xlo, *p_yhi, *p_ylo;
    cudaGetSymbolAddress((void**)&p_qkv, g_qkv);
    cudaGetSymbolAddress((void**)&p_q,   g_q);
    cudaGetSymbolAddress((void**)&p_k,   g_k);
    cudaGetSymbolAddress((void**)&p_v,   g_v);
    cudaGetSymbolAddress((void**)&p_y,   g_y);
    cudaGetSymbolAddress((void**)&p_whi, g_whi);
    cudaGetSymbolAddress((void**)&p_wlo, g_wlo);
    cudaGetSymbolAddress((void**)&p_xhi, g_xhi);
    cudaGetSymbolAddress((void**)&p_xlo, g_xlo);
    cudaGetSymbolAddress((void**)&p_yhi, g_yhi);
    cudaGetSymbolAddress((void**)&p_ylo, g_ylo);

    static const int ATTN_SMEM = (8192 + 8704 + 8192 + 4352) * 4;
    cudaFuncSetAttribute(attn_kernel, cudaFuncAttributeMaxDynamicSharedMemorySize, ATTN_SMEM);
    cudaFuncSetAttribute(gemm_bf16x3, cudaFuncAttributeMaxDynamicSharedMemorySize, GEMM_SMEM);

    // 0) split weights + x into bf16 hi/lo
    split_kernel<<<(4*DIM*DIM)/1024, 256>>>((const float4*)w, (uint2*)p_whi, (uint2*)p_wlo, 4*DIM*DIM/4);
    split_kernel<<<(T_LEN*DIM)/1024, 256>>>((const float4*)x, (uint2*)p_xhi, (uint2*)p_xlo, T_LEN*DIM/4);

    // 1) qkv = x @ W_qkv^T : [2048, 6144]
    gemm_bf16x3<<<dim3(3*DIM/128, T_LEN/128), 256, GEMM_SMEM>>>(
        p_xhi, p_xlo, p_whi, p_wlo, p_qkv, T_LEN, 3*DIM, DIM);

    // 2) rmsnorm + rope + v-mix
    fuse_kernel<<<dim3(T_LEN, NHEAD), 128>>>(p_qkv, ve, lambdas, p_q, p_k, p_v);

    // 3) causal attention
    attn_kernel<<<dim3(T_LEN/64, NHEAD), 256, ATTN_SMEM>>>(p_q, p_k, p_v, p_y);

    // 4) split y, then out = y @ W_o^T : [2048, 2048]
    split_kernel<<<(T_LEN*DIM)/1024, 256>>>((const float4*)p_y, (uint2*)p_yhi, (uint2*)p_ylo, T_LEN*DIM/4);
    gemm_bf16x3<<<dim3(DIM/128, T_LEN/128), 256, GEMM_SMEM>>>(
        p_yhi, p_ylo, p_whi + (size_t)3*DIM*DIM, p_wlo + (size_t)3*DIM*DIM, out, T_LEN, DIM, DIM);
}

// round 7
// speedup vs baseline: 2.6366x; 1.6107x over previous
#include <cuda_runtime.h>
#include <cuda_bf16.h>
#include <math.h>
#include <stdint.h>

#define DIM 2048
#define T_LEN 2048
#define NHEAD 16
#define HDIM 128
#define ATTN_SCALE 0.12f

// ---------------- scratch ----------------
__device__ float g_qkv[T_LEN * 3 * DIM];        // [t][e*2048 + h*128 + d]
__device__ __nv_bfloat16 g_whi[4 * DIM * DIM];
__device__ __nv_bfloat16 g_wlo[4 * DIM * DIM];
__device__ __nv_bfloat16 g_xhi[T_LEN * DIM];
__device__ __nv_bfloat16 g_xlo[T_LEN * DIM];
__device__ __nv_bfloat16 g_yhi[T_LEN * DIM];
__device__ __nv_bfloat16 g_ylo[T_LEN * DIM];
// attention operands, [h][t][d] bf16 hi/lo
__device__ __nv_bfloat16 g_qh[NHEAD * T_LEN * HDIM];
__device__ __nv_bfloat16 g_ql[NHEAD * T_LEN * HDIM];
__device__ __nv_bfloat16 g_kh[NHEAD * T_LEN * HDIM];
__device__ __nv_bfloat16 g_kl[NHEAD * T_LEN * HDIM];
__device__ __nv_bfloat16 g_vh[NHEAD * T_LEN * HDIM];
__device__ __nv_bfloat16 g_vl[NHEAD * T_LEN * HDIM];

// ---------------- PTX helpers (portable sm_80+) ----------------
__device__ __forceinline__ uint32_t smem_to_u32(const void* p) {
    uint32_t a;
    asm("{ .reg .u64 t; cvta.to.shared.u64 t, %1; cvt.u32.u64 %0, t; }" : "=r"(a) : "l"(p));
    return a;
}
__device__ __forceinline__ void cp16(uint32_t dst, const void* src) {
    asm volatile("cp.async.cg.shared.global [%0], [%1], 16;" :: "r"(dst), "l"(src) : "memory");
}
__device__ __forceinline__ void ldsm4(uint32_t* r, uint32_t a) {
    asm volatile("ldmatrix.sync.aligned.m8n8.x4.shared.b16 {%0,%1,%2,%3}, [%4];"
        : "=r"(r[0]), "=r"(r[1]), "=r"(r[2]), "=r"(r[3]) : "r"(a));
}
__device__ __forceinline__ void ldsm2(uint32_t* r, uint32_t a) {
    asm volatile("ldmatrix.sync.aligned.m8n8.x2.shared.b16 {%0,%1}, [%2];"
        : "=r"(r[0]), "=r"(r[1]) : "r"(a));
}
__device__ __forceinline__ void ldsm2t(uint32_t* r, uint32_t a) {
    asm volatile("ldmatrix.sync.aligned.m8n8.x2.trans.shared.b16 {%0,%1}, [%2];"
        : "=r"(r[0]), "=r"(r[1]) : "r"(a));
}
__device__ __forceinline__ void mma16816(float* d, const uint32_t* a, const uint32_t* b) {
    asm volatile("mma.sync.aligned.m16n8k16.row.col.f32.bf16.bf16.f32 "
        "{%0,%1,%2,%3}, {%4,%5,%6,%7}, {%8,%9}, {%0,%1,%2,%3};"
        : "+f"(d[0]), "+f"(d[1]), "+f"(d[2]), "+f"(d[3])
        : "r"(a[0]), "r"(a[1]), "r"(a[2]), "r"(a[3]), "r"(b[0]), "r"(b[1]));
}

// fast e^x for x <= 0 (FMA pipe only, rel err ~2e-6)
__device__ __forceinline__ float fexp(float x) {
    float t = fmaxf(x * 1.4426950408889634f, -80.0f);
    float z = t + 12582912.0f;                 // round-to-nearest-int trick
    float f = t - (z - 12582912.0f);           // frac in [-0.5, 0.5]
    int  i = __float_as_int(z) - 0x4B400000;   // integer part
    float p = 1.3333558146e-3f;
    p = fmaf(p, f, 9.6181291076e-3f);
    p = fmaf(p, f, 5.5504108664e-2f);
    p = fmaf(p, f, 2.4022650696e-1f);
    p = fmaf(p, f, 6.9314718056e-1f);
    p = fmaf(p, f, 1.0f);
    return __int_as_float(__float_as_int(p) + (i << 23));
}

// ---------------- fp32 -> bf16 hi/lo split ----------------
__global__ __launch_bounds__(256) void split_kernel(
    const float4* __restrict__ src, uint2* __restrict__ hi, uint2* __restrict__ lo, int n4)
{
    int i = blockIdx.x * 256 + threadIdx.x;
    if (i >= n4) return;
    float4 v = src[i];
    float a[4] = {v.x, v.y, v.z, v.w};
    uint32_t hb[4], lb[4];
    #pragma unroll
    for (int u = 0; u < 4; u++) {
        __nv_bfloat16 h = __float2bfloat16(a[u]);
        float l = a[u] - __bfloat162float(h);
        __nv_bfloat16 lo16 = __float2bfloat16(l);
        hb[u] = (uint32_t)__bfloat16_as_ushort(h);
        lb[u] = (uint32_t)__bfloat16_as_ushort(lo16);
    }
    uint2 H, L;
    H.x = hb[0] | (hb[1] << 16); H.y = hb[2] | (hb[3] << 16);
    L.x = lb[0] | (lb[1] << 16); L.y = lb[2] | (lb[3] << 16);
    hi[i] = H; lo[i] = L;
}

// ---------------- bf16x3 HMMA GEMM (unchanged from R6) ----------------
#define GKC 32
#define ROWB 80
#define AHI_OFF 0
#define ALO_OFF 10240
#define BHI_OFF 20480
#define BLO_OFF 30720
#define STAGE_BYTES 40960
#define GEMM_SMEM (2 * STAGE_BYTES)

__global__ __launch_bounds__(256, 1) void gemm_bf16x3(
    const __nv_bfloat16* __restrict__ Ahi, const __nv_bfloat16* __restrict__ Alo,
    const __nv_bfloat16* __restrict__ Bhi, const __nv_bfloat16* __restrict__ Blo,
    float* __restrict__ C, int M, int N, int K)
{
    extern __shared__ char smc[];
    uint32_t smem_base = smem_to_u32(smc);
    int tid = threadIdx.x, wid = tid >> 5, lane = tid & 31;
    int m0 = blockIdx.y * 128, n0 = blockIdx.x * 128;
    int wy = wid & 1, wx = wid >> 1;
    int mb = wy * 64, nb = wx * 32;

    uint32_t arow = (uint32_t)((lane & 15) * ROWB + ((lane >> 4) & 1) * 16);
    uint32_t brow = (uint32_t)((lane & 7) * ROWB + ((lane >> 3) & 1) * 16);

    float acc[4][4][4];
    #pragma unroll
    for (int i = 0; i < 4; i++)
        #pragma unroll
        for (int j = 0; j < 4; j++)
            #pragma unroll
            for (int u = 0; u < 4; u++) acc[i][j][u] = 0.0f;

    auto fill_async = [&](int s, int k0) {
        uint32_t sb = smem_base + s * STAGE_BYTES;
        #pragma unroll
        for (int rep = 0; rep < 2; rep++) {
            int i = tid + rep * 256;
            int row = i >> 2, seg = i & 3;
            uint32_t doff = (uint32_t)(row * ROWB + seg * 16);
            size_t ga = (size_t)(m0 + row) * K + k0 + seg * 8;
            size_t gb = (size_t)(n0 + row) * K + k0 + seg * 8;
            cp16(sb + AHI_OFF + doff, Ahi + ga);
            cp16(sb + ALO_OFF + doff, Alo + ga);
            cp16(sb + BHI_OFF + doff, Bhi + gb);
            cp16(sb + BLO_OFF + doff, Blo + gb);
        }
    };

    const int nchunks = K / GKC;
    fill_async(0, 0);
    asm volatile("cp.async.commit_group;" ::: "memory");
    asm volatile("cp.async.wait_group 0;" ::: "memory");
    __syncthreads();

    for (int c = 0; c < nchunks; c++) {
        if (c + 1 < nchunks) fill_async((c + 1) & 1, (c + 1) * GKC);
        asm volatile("cp.async.commit_group;" ::: "memory");

        uint32_t sb = smem_base + (c & 1) * STAGE_BYTES;
        #pragma unroll
        for (int ks = 0; ks < 2; ks++) {
            uint32_t ah[4][4], al[4][4], bh[4][2], bl[4][2];
            #pragma unroll
            for (int mi = 0; mi < 4; mi++) {
                uint32_t base = sb + (uint32_t)((mb + mi * 16) * ROWB + ks * 32) + arow;
                ldsm4(ah[mi], base + AHI_OFF);
                ldsm4(al[mi], base + ALO_OFF);
            }
            #pragma unroll
            for (int ni = 0; ni < 4; ni++) {
                uint32_t base = sb + (uint32_t)((nb + ni * 8) * ROWB + ks * 32) + brow;
                ldsm2(bh[ni], base + BHI_OFF);
                ldsm2(bl[ni], base + BLO_OFF);
            }
            #pragma unroll
            for (int mi = 0; mi < 4; mi++)
                #pragma unroll
                for (int ni = 0; ni < 4; ni++) {
                    mma16816(acc[mi][ni], ah[mi], bh[ni]);
                    mma16816(acc[mi][ni], ah[mi], bl[ni]);
                    mma16816(acc[mi][ni], al[mi], bh[ni]);
                }
        }
        asm volatile("cp.async.wait_group 0;" ::: "memory");
        __syncthreads();
    }

    int r0 = lane >> 2, c2 = (lane & 3) * 2;
    #pragma unroll
    for (int mi = 0; mi < 4; mi++) {
        int rowa = m0 + mb + mi * 16 + r0;
        #pragma unroll
        for (int ni = 0; ni < 4; ni++) {
            int col = n0 + nb + ni * 8 + c2;
            *(float2*)(C + (size_t)rowa * N + col) = make_float2(acc[mi][ni][0], acc[mi][ni][1]);
            *(float2*)(C + (size_t)(rowa + 8) * N + col) = make_float2(acc[mi][ni][2], acc[mi][ni][3]);
        }
    }
}

// ---------------- RMSNorm + RoPE + v-mix -> bf16 hi/lo ----------------
__global__ __launch_bounds__(128) void fuse_kernel(
    const float* __restrict__ qkv, const float* __restrict__ ve,
    const float* __restrict__ lambdas,
    __nv_bfloat16* __restrict__ Qh, __nv_bfloat16* __restrict__ Ql,
    __nv_bfloat16* __restrict__ Kh, __nv_bfloat16* __restrict__ Kl,
    __nv_bfloat16* __restrict__ Vh, __nv_bfloat16* __restrict__ Vl)
{
    int t = blockIdx.x, h = blockIdx.y, d = threadIdx.x;
    size_t base = (size_t)t * (3*DIM) + h * HDIM + d;
    float q = qkv[base];
    float k = qkv[base + DIM];
    float v = qkv[base + 2*DIM];

    __shared__ float red[3][4];
    __shared__ float qn_s[128], kn_s[128];
    float sq = q*q, sk = k*k, sv = v*v;
    #pragma unroll
    for (int off = 16; off > 0; off >>= 1) {
        sq += __shfl_xor_sync(0xffffffffu, sq, off);
        sk += __shfl_xor_sync(0xffffffffu, sk, off);
        sv += __shfl_xor_sync(0xffffffffu, sv, off);
    }
    int warp = d >> 5, lane = d & 31;
    if (lane == 0) { red[0][warp] = sq; red[1][warp] = sk; red[2][warp] = sv; }
    __syncthreads();
    sq = red[0][0]+red[0][1]+red[0][2]+red[0][3];
    sk = red[1][0]+red[1][1]+red[1][2]+red[1][3];
    sv = red[2][0]+red[2][1]+red[2][2]+red[2][3];
    float rq = rsqrtf(sq * (1.0f/128.0f) + 1e-6f);
    float rk = rsqrtf(sk * (1.0f/128.0f) + 1e-6f);
    float rv = rsqrtf(sv * (1.0f/128.0f) + 1e-6f);
    float qn = q * rq, kn = k * rk, vn = v * rv;
    qn_s[d] = qn; kn_s[d] = kn;
    __syncthreads();

    int j = (d < 64) ? d : (d - 64);
    float f = (j < 32) ? exp2f(-10.0f * (float)j / 31.0f) : 0.0f;
    float th = (float)t * f;
    float sn, cs;
    sincosf(th, &sn, &cs);
    float oq, ok;
    if (d < 64) {
        oq =  qn * cs + qn_s[d+64] * sn;
        ok =  kn * cs + kn_s[d+64] * sn;
    } else {
        oq = -qn_s[d-64] * sn + qn * cs;
        ok = -kn_s[d-64] * sn + kn * cs;
    }
    float l0 = lambdas[0], l1 = lambdas[1];
    float vm = l0 * vn + l1 * ve[(size_t)t * DIM + h * HDIM + d];

    size_t oidx = ((size_t)h * T_LEN + t) * HDIM + d;
    float oqs = oq * ATTN_SCALE;   // fold attention scale into Q
    __nv_bfloat16 qhh = __float2bfloat16(oqs);
    __nv_bfloat16 khh = __float2bfloat16(ok);
    __nv_bfloat16 vhh = __float2bfloat16(vm);
    Qh[oidx] = qhh; Ql[oidx] = __float2bfloat16(oqs - __bfloat162float(qhh));
    Kh[oidx] = khh; Kl[oidx] = __float2bfloat16(ok - __bfloat162float(khh));
    Vh[oidx] = vhh; Vl[oidx] = __float2bfloat16(vm - __bfloat162float(vhh));
}

// ---------------- bf16x3 HMMA causal flash attention ----------------
// BQ=128 (8 warps x 16 rows), BK=64, D=128. K/V double-buffered via cp.async.
#define AT_ROWB 272                 // 136 bf16 padded row
#define QS_HI 0
#define QS_LO 34816                 // 128*272
#define KV_BASE 69632
#define ST_KHI 0
#define ST_KLO 17408
#define ST_VHI 34816
#define ST_VLO 52224
#define ST_BYTES 69632
#define ATTN_SMEM (KV_BASE + 2 * ST_BYTES)   // 208896

__global__ __launch_bounds__(256, 1) void attn_mma(
    const __nv_bfloat16* __restrict__ Qh, const __nv_bfloat16* __restrict__ Ql,
    const __nv_bfloat16* __restrict__ Kh, const __nv_bfloat16* __restrict__ Kl,
    const __nv_bfloat16* __restrict__ Vh, const __nv_bfloat16* __restrict__ Vl,
    __nv_bfloat16* __restrict__ Yh, __nv_bfloat16* __restrict__ Yl)
{
    extern __shared__ char smc[];
    uint32_t sb = smem_to_u32(smc);
    int tid = threadIdx.x, w = tid >> 5, lane = tid & 31;
    int qt = 15 - (int)blockIdx.x;          // heavy tiles first
    int h = blockIdx.y;
    int q0 = qt * 128, nkt = 2 * qt + 2;
    int g = lane >> 2;
    size_t hb = (size_t)h * T_LEN * HDIM;

    // prologue: stage Q (hi/lo) and KV tile 0
    {
        const __nv_bfloat16* qsrc = Qh + hb + (size_t)q0 * HDIM;
        const __nv_bfloat16* lsrc = Ql + hb + (size_t)q0 * HDIM;
        #pragma unroll
        for (int rep = 0; rep < 8; rep++) {
            int i = tid + rep * 256;
            int row = i >> 4, ch = i & 15;
            uint32_t d = (uint32_t)(row * AT_ROWB + ch * 16);
            cp16(sb + QS_HI + d, qsrc + row * HDIM + ch * 8);
            cp16(sb + QS_LO + d, lsrc + row * HDIM + ch * 8);
        }
    }
    auto fillKV = [&](int s, int kt) {
        uint32_t b = sb + KV_BASE + s * ST_BYTES;
        size_t base = hb + (size_t)kt * 64 * HDIM;
        #pragma unroll
        for (int rep = 0; rep < 4; rep++) {
            int i = tid + rep * 256;
            int row = i >> 4, ch = i & 15;
            uint32_t d = (uint32_t)(row * AT_ROWB + ch * 16);
            size_t so = base + row * HDIM + ch * 8;
            cp16(b + ST_KHI + d, Kh + so);
            cp16(b + ST_KLO + d, Kl + so);
            cp16(b + ST_VHI + d, Vh + so);
            cp16(b + ST_VLO + d, Vl + so);
        }
    };
    fillKV(0, 0);
    asm volatile("cp.async.commit_group;" ::: "memory");

    float o[16][4];
    #pragma unroll
    for (int jn = 0; jn < 16; jn++)
        #pragma unroll
        for (int u = 0; u < 4; u++) o[jn][u] = 0.0f;
    float m0 = -1e30f, m1 = -1e30f, l0 = 0.0f, l1 = 0.0f;

    for (int kt = 0; kt < nkt; kt++) {
        asm volatile("cp.async.wait_group 0;" ::: "memory");
        __syncthreads();
        if (kt + 1 < nkt) {
            fillKV((kt + 1) & 1, kt + 1);
            asm volatile("cp.async.commit_group;" ::: "memory");
        }
        if (kt * 64 > q0 + w * 16 + 15) continue;   // warp fully above diagonal
        uint32_t kvs = sb + KV_BASE + (kt & 1) * ST_BYTES;

        // ---- S = Q K^T (3-term bf16x3) ----
        float c[8][4];
        #pragma unroll
        for (int jn = 0; jn < 8; jn++)
            #pragma unroll
            for (int u = 0; u < 4; u++) c[jn][u] = 0.0f;

        {
            uint32_t qh[4], ql_[4], bh[2], bl[2];
            #pragma unroll 2
            for (int ks = 0; ks < 8; ks++) {
                uint32_t qa = sb + (uint32_t)((w * 16 + (lane & 15)) * AT_ROWB + ks * 32 + (lane >> 4) * 16);
                ldsm4(qh, qa + QS_HI);
                ldsm4(ql_, qa + QS_LO);
                #pragma unroll
                for (int jn = 0; jn < 8; jn++) {
                    uint32_t ka = kvs + (uint32_t)((jn * 8 + (lane & 7)) * AT_ROWB + ks * 32 + ((lane >> 3) & 1) * 16);
                    ldsm2(bh, ka + ST_KHI);
                    ldsm2(bl, ka + ST_KLO);
                    mma16816(c[jn], qh, bh);
                    mma16816(c[jn], qh, bl);
                    mma16816(c[jn], ql_, bh);
                }
            }
        }

        // ---- causal mask ----
        if (kt * 64 + 63 > q0 + w * 16) {
            int r0 = q0 + w * 16 + g;
            #pragma unroll
            for (int jn = 0; jn < 8; jn++) {
                int cb = kt * 64 + jn * 8 + (lane & 3) * 2;
                if (cb     > r0)     c[jn][0] = -1e30f;
                if (cb + 1 > r0)     c[jn][1] = -1e30f;
                if (cb     > r0 + 8) c[jn][2] = -1e30f;
                if (cb + 1 > r0 + 8) c[jn][3] = -1e30f;
            }
        }

        // ---- online softmax ----
        float mx0 = -1e30f, mx1 = -1e30f;
        #pragma unroll
        for (int jn = 0; jn < 8; jn++) {
            mx0 = fmaxf(mx0, fmaxf(c[jn][0], c[jn][1]));
            mx1 = fmaxf(mx1, fmaxf(c[jn][2], c[jn][3]));
        }
        mx0 = fmaxf(mx0, __shfl_xor_sync(0xffffffffu, mx0, 1));
        mx0 = fmaxf(mx0, __shfl_xor_sync(0xffffffffu, mx0, 2));
        mx1 = fmaxf(mx1, __shfl_xor_sync(0xffffffffu, mx1, 1));
        mx1 = fmaxf(mx1, __shfl_xor_sync(0xffffffffu, mx1, 2));
        float mn0 = fmaxf(m0, mx0), mn1 = fmaxf(m1, mx1);
        float a0 = fexp(m0 - mn0), a1 = fexp(m1 - mn1);
        m0 = mn0; m1 = mn1;
        l0 *= a0; l1 *= a1;
        #pragma unroll
        for (int jn = 0; jn < 16; jn++) {
            o[jn][0] *= a0; o[jn][1] *= a0;
            o[jn][2] *= a1; o[jn][3] *= a1;
        }
        float rs0 = 0.0f, rs1 = 0.0f;
        #pragma unroll
        for (int jn = 0; jn < 8; jn++) {
            c[jn][0] = fexp(c[jn][0] - mn0);
            c[jn][1] = fexp(c[jn][1] - mn0);
            c[jn][2] = fexp(c[jn][2] - mn1);
            c[jn][3] = fexp(c[jn][3] - mn1);
            rs0 += c[jn][0] + c[jn][1];
            rs1 += c[jn][2] + c[jn][3];
        }
        rs0 += __shfl_xor_sync(0xffffffffu, rs0, 1);
        rs0 += __shfl_xor_sync(0xffffffffu, rs0, 2);
        rs1 += __shfl_xor_sync(0xffffffffu, rs1, 1);
        rs1 += __shfl_xor_sync(0xffffffffu, rs1, 2);
        l0 += rs0; l1 += rs1;

        // ---- O += P V (3-term: Phi*Vhi + Phi*Vlo + Plo*Vhi) ----
        #pragma unroll
        for (int kk = 0; kk < 4; kk++) {
            uint32_t ah[4], al[4];
            #pragma unroll
            for (int half = 0; half < 2; half++) {
                int t2 = 2 * kk + half;
                __nv_bfloat162 h01 = __floats2bfloat162_rn(c[t2][0], c[t2][1]);
                __nv_bfloat162 h23 = __floats2bfloat162_rn(c[t2][2], c[t2][3]);
                __nv_bfloat162 L01 = __floats2bfloat162_rn(
                    c[t2][0] - __bfloat162float(h01.x), c[t2][1] - __bfloat162float(h01.y));
                __nv_bfloat162 L23 = __floats2bfloat162_rn(
                    c[t2][2] - __bfloat162float(h23.x), c[t2][3] - __bfloat162float(h23.y));
                ah[half * 2 + 0] = *(uint32_t*)&h01;
                ah[half * 2 + 1] = *(uint32_t*)&h23;
                al[half * 2 + 0] = *(uint32_t*)&L01;
                al[half * 2 + 1] = *(uint32_t*)&L23;
            }
            // a-frag ordering: a0=(r,k0-7) a1=(r+8,k0-7) a2=(r,k8-15) a3=(r+8,k8-15)
            uint32_t af_h[4] = {ah[0], ah[1], ah[2], ah[3]};
            uint32_t af_l[4] = {al[0], al[1], al[2], al[3]};
            uint32_t bh[2], bl[2];
            #pragma unroll
            for (int jn = 0; jn < 16; jn++) {
                uint32_t va = kvs + (uint32_t)((kk * 16 + (lane & 15)) * AT_ROWB + jn * 16);
                ldsm2t(bh, va + ST_VHI);
                ldsm2t(bl, va + ST_VLO);
                mma16816(o[jn], af_h, bh);
                mma16816(o[jn], af_h, bl);
                mma16816(o[jn], af_l, bh);
            }
        }
    }

    // ---- epilogue: normalize + write y as bf16 hi/lo ----
    float inv0 = 1.0f / l0, inv1 = 1.0f / l1;
    int r0 = q0 + w * 16 + g;
    #pragma unroll
    for (int jn = 0; jn < 16; jn++) {
        int col = h * HDIM + jn * 8 + (lane & 3) * 2;
        float v0 = o[jn][0] * inv0, v1 = o[jn][1] * inv0;
        float v2 = o[jn][2] * inv1, v3 = o[jn][3] * inv1;
        __nv_bfloat162 h01 = __floats2bfloat162_rn(v0, v1);
        __nv_bfloat162 L01 = __floats2bfloat162_rn(v0 - __bfloat162float(h01.x),
                                                   v1 - __bfloat162float(h01.y));
        __nv_bfloat162 h23 = __floats2bfloat162_rn(v2, v3);
        __nv_bfloat162 L23 = __floats2bfloat162_rn(v2 - __bfloat162float(h23.x),
                                                   v3 - __bfloat162float(h23.y));
        *(__nv_bfloat162*)(Yh + (size_t)r0 * DIM + col) = h01;
        *(__nv_bfloat162*)(Yl + (size_t)r0 * DIM + col) = L01;
        *(__nv_bfloat162*)(Yh + (size_t)(r0 + 8) * DIM + col) = h23;
        *(__nv_bfloat162*)(Yl + (size_t)(r0 + 8) * DIM + col) = L23;
    }
}

// ---------------- launch ----------------
extern "C" void kernel_launch(void* const* d_in, const int* in_sizes, int n_in,
                              void* d_out, int out_size)
{
    const float* x       = (const float*)d_in[0];
    const float* w       = (const float*)d_in[1];   // [4,2048,2048]
    const float* ve      = (const float*)d_in[2];
    const float* lambdas = (const float*)d_in[3];
    float* out = (float*)d_out;

    float *p_qkv;
    __nv_bfloat16 *p_whi, *p_wlo, *p_xhi, *p_xlo, *p_yhi, *p_ylo;
    __nv_bfloat16 *p_qh, *p_ql, *p_kh, *p_kl, *p_vh, *p_vl;
    cudaGetSymbolAddress((void**)&p_qkv, g_qkv);
    cudaGetSymbolAddress((void**)&p_whi, g_whi);
    cudaGetSymbolAddress((void**)&p_wlo, g_wlo);
    cudaGetSymbolAddress((void**)&p_xhi, g_xhi);
    cudaGetSymbolAddress((void**)&p_xlo, g_xlo);
    cudaGetSymbolAddress((void**)&p_yhi, g_yhi);
    cudaGetSymbolAddress((void**)&p_ylo, g_ylo);
    cudaGetSymbolAddress((void**)&p_qh, g_qh);
    cudaGetSymbolAddress((void**)&p_ql, g_ql);
    cudaGetSymbolAddress((void**)&p_kh, g_kh);
    cudaGetSymbolAddress((void**)&p_kl, g_kl);
    cudaGetSymbolAddress((void**)&p_vh, g_vh);
    cudaGetSymbolAddress((void**)&p_vl, g_vl);

    cudaFuncSetAttribute(gemm_bf16x3, cudaFuncAttributeMaxDynamicSharedMemorySize, GEMM_SMEM);
    cudaFuncSetAttribute(attn_mma, cudaFuncAttributeMaxDynamicSharedMemorySize, ATTN_SMEM);

    // 0) split weights + x into bf16 hi/lo
    split_kernel<<<(4*DIM*DIM)/1024, 256>>>((const float4*)w, (uint2*)p_whi, (uint2*)p_wlo, 4*DIM*DIM/4);
    split_kernel<<<(T_LEN*DIM)/1024, 256>>>((const float4*)x, (uint2*)p_xhi, (uint2*)p_xlo, T_LEN*DIM/4);

    // 1) qkv = x @ W_qkv^T : [2048, 6144]
    gemm_bf16x3<<<dim3(3*DIM/128, T_LEN/128), 256, GEMM_SMEM>>>(
        p_xhi, p_xlo, p_whi, p_wlo, p_qkv, T_LEN, 3*DIM, DIM);

    // 2) rmsnorm + rope + v-mix -> bf16 hi/lo Q(scaled), K, V
    fuse_kernel<<<dim3(T_LEN, NHEAD), 128>>>(p_qkv, ve, lambdas,
        p_qh, p_ql, p_kh, p_kl, p_vh, p_vl);

    // 3) causal attention (tensor cores) -> y bf16 hi/lo
    attn_mma<<<dim3(16, NHEAD), 256, ATTN_SMEM>>>(
        p_qh, p_ql, p_kh, p_kl, p_vh, p_vl, p_yhi, p_ylo);

    // 4) out = y @ W_o^T : [2048, 2048]
    gemm_bf16x3<<<dim3(DIM/128, T_LEN/128), 256, GEMM_SMEM>>>(
        p_yhi, p_ylo, p_whi + (size_t)3*DIM*DIM, p_wlo + (size_t)3*DIM*DIM, out, T_LEN, DIM, DIM);
}

// round 8
// speedup vs baseline: 3.0123x; 1.1425x over previous
#include <cuda_runtime.h>
#include <cuda_bf16.h>
#include <math.h>
#include <stdint.h>

#define DIM 2048
#define T_LEN 2048
#define NHEAD 16
#define HDIM 128
#define ATTN_SCALE 0.12f

// ---------------- scratch ----------------
__device__ float g_qkv[T_LEN * 3 * DIM];        // [t][e*2048 + h*128 + d]
__device__ __nv_bfloat16 g_whi[4 * DIM * DIM];
__device__ __nv_bfloat16 g_wlo[4 * DIM * DIM];
__device__ __nv_bfloat16 g_xhi[T_LEN * DIM];
__device__ __nv_bfloat16 g_xlo[T_LEN * DIM];
__device__ __nv_bfloat16 g_yhi[T_LEN * DIM];
__device__ __nv_bfloat16 g_ylo[T_LEN * DIM];
// attention operands, [h][t][d] bf16 hi/lo
__device__ __nv_bfloat16 g_qh[NHEAD * T_LEN * HDIM];
__device__ __nv_bfloat16 g_ql[NHEAD * T_LEN * HDIM];
__device__ __nv_bfloat16 g_kh[NHEAD * T_LEN * HDIM];
__device__ __nv_bfloat16 g_kl[NHEAD * T_LEN * HDIM];
__device__ __nv_bfloat16 g_vh[NHEAD * T_LEN * HDIM];
__device__ __nv_bfloat16 g_vl[NHEAD * T_LEN * HDIM];

// ---------------- PTX helpers (portable sm_80+) ----------------
__device__ __forceinline__ uint32_t smem_to_u32(const void* p) {
    uint32_t a;
    asm("{ .reg .u64 t; cvta.to.shared.u64 t, %1; cvt.u32.u64 %0, t; }" : "=r"(a) : "l"(p));
    return a;
}
__device__ __forceinline__ void cp16(uint32_t dst, const void* src) {
    asm volatile("cp.async.cg.shared.global [%0], [%1], 16;" :: "r"(dst), "l"(src) : "memory");
}
__device__ __forceinline__ void ldsm4(uint32_t* r, uint32_t a) {
    asm volatile("ldmatrix.sync.aligned.m8n8.x4.shared.b16 {%0,%1,%2,%3}, [%4];"
        : "=r"(r[0]), "=r"(r[1]), "=r"(r[2]), "=r"(r[3]) : "r"(a));
}
__device__ __forceinline__ void ldsm2(uint32_t* r, uint32_t a) {
    asm volatile("ldmatrix.sync.aligned.m8n8.x2.shared.b16 {%0,%1}, [%2];"
        : "=r"(r[0]), "=r"(r[1]) : "r"(a));
}
__device__ __forceinline__ void ldsm2t(uint32_t* r, uint32_t a) {
    asm volatile("ldmatrix.sync.aligned.m8n8.x2.trans.shared.b16 {%0,%1}, [%2];"
        : "=r"(r[0]), "=r"(r[1]) : "r"(a));
}
__device__ __forceinline__ void mma16816(float* d, const uint32_t* a, const uint32_t* b) {
    asm volatile("mma.sync.aligned.m16n8k16.row.col.f32.bf16.bf16.f32 "
        "{%0,%1,%2,%3}, {%4,%5,%6,%7}, {%8,%9}, {%0,%1,%2,%3};"
        : "+f"(d[0]), "+f"(d[1]), "+f"(d[2]), "+f"(d[3])
        : "r"(a[0]), "r"(a[1]), "r"(a[2]), "r"(a[3]), "r"(b[0]), "r"(b[1]));
}

// fast e^x for x <= 0 (FMA pipe only, rel err ~2e-6)
__device__ __forceinline__ float fexp(float x) {
    float t = fmaxf(x * 1.4426950408889634f, -80.0f);
    float z = t + 12582912.0f;
    float f = t - (z - 12582912.0f);
    int  i = __float_as_int(z) - 0x4B400000;
    float p = 1.3333558146e-3f;
    p = fmaf(p, f, 9.6181291076e-3f);
    p = fmaf(p, f, 5.5504108664e-2f);
    p = fmaf(p, f, 2.4022650696e-1f);
    p = fmaf(p, f, 6.9314718056e-1f);
    p = fmaf(p, f, 1.0f);
    return __int_as_float(__float_as_int(p) + (i << 23));
}

// ---------------- fp32 -> bf16 hi/lo split ----------------
__global__ __launch_bounds__(256) void split_kernel(
    const float4* __restrict__ src, uint2* __restrict__ hi, uint2* __restrict__ lo, int n4)
{
    int i = blockIdx.x * 256 + threadIdx.x;
    if (i >= n4) return;
    float4 v = src[i];
    float a[4] = {v.x, v.y, v.z, v.w};
    uint32_t hb[4], lb[4];
    #pragma unroll
    for (int u = 0; u < 4; u++) {
        __nv_bfloat16 h = __float2bfloat16(a[u]);
        float l = a[u] - __bfloat162float(h);
        __nv_bfloat16 lo16 = __float2bfloat16(l);
        hb[u] = (uint32_t)__bfloat16_as_ushort(h);
        lb[u] = (uint32_t)__bfloat16_as_ushort(lo16);
    }
    uint2 H, L;
    H.x = hb[0] | (hb[1] << 16); H.y = hb[2] | (hb[3] << 16);
    L.x = lb[0] | (lb[1] << 16); L.y = lb[2] | (lb[3] << 16);
    hi[i] = H; lo[i] = L;
}

// ---------------- bf16x3 HMMA GEMM: C[M,N] = A[M,K] * B[N,K]^T ----------------
// CTA 128x128, 8 warps (64x32 warp tiles), K-chunk 32, double buffer, 2 CTAs/SM.
#define GKC 32
#define ROWB 80
#define AHI_OFF 0
#define ALO_OFF 10240
#define BHI_OFF 20480
#define BLO_OFF 30720
#define STAGE_BYTES 40960
#define GEMM_SMEM (2 * STAGE_BYTES)

__global__ __launch_bounds__(256, 2) void gemm_bf16x3(
    const __nv_bfloat16* __restrict__ Ahi, const __nv_bfloat16* __restrict__ Alo,
    const __nv_bfloat16* __restrict__ Bhi, const __nv_bfloat16* __restrict__ Blo,
    float* __restrict__ C, int M, int N, int K)
{
    extern __shared__ char smc[];
    uint32_t smem_base = smem_to_u32(smc);
    int tid = threadIdx.x, wid = tid >> 5, lane = tid & 31;
    int m0 = blockIdx.y * 128, n0 = blockIdx.x * 128;
    int wy = wid & 1, wx = wid >> 1;
    int mb = wy * 64, nb = wx * 32;

    uint32_t arow = (uint32_t)((lane & 15) * ROWB + ((lane >> 4) & 1) * 16);
    uint32_t brow = (uint32_t)((lane & 7) * ROWB + ((lane >> 3) & 1) * 16);

    float acc[4][4][4];
    #pragma unroll
    for (int i = 0; i < 4; i++)
        #pragma unroll
        for (int j = 0; j < 4; j++)
            #pragma unroll
            for (int u = 0; u < 4; u++) acc[i][j][u] = 0.0f;

    auto fill_async = [&](int s, int k0) {
        uint32_t sb = smem_base + s * STAGE_BYTES;
        #pragma unroll
        for (int rep = 0; rep < 2; rep++) {
            int i = tid + rep * 256;
            int row = i >> 2, seg = i & 3;
            uint32_t doff = (uint32_t)(row * ROWB + seg * 16);
            size_t ga = (size_t)(m0 + row) * K + k0 + seg * 8;
            size_t gb = (size_t)(n0 + row) * K + k0 + seg * 8;
            cp16(sb + AHI_OFF + doff, Ahi + ga);
            cp16(sb + ALO_OFF + doff, Alo + ga);
            cp16(sb + BHI_OFF + doff, Bhi + gb);
            cp16(sb + BLO_OFF + doff, Blo + gb);
        }
    };

    const int nchunks = K / GKC;
    fill_async(0, 0);
    asm volatile("cp.async.commit_group;" ::: "memory");
    asm volatile("cp.async.wait_group 0;" ::: "memory");
    __syncthreads();

    for (int c = 0; c < nchunks; c++) {
        if (c + 1 < nchunks) fill_async((c + 1) & 1, (c + 1) * GKC);
        asm volatile("cp.async.commit_group;" ::: "memory");

        uint32_t sb = smem_base + (c & 1) * STAGE_BYTES;
        #pragma unroll
        for (int ks = 0; ks < 2; ks++) {
            // A fragments for this k-step (32 regs), B streamed per-ni (4 regs)
            uint32_t ah[4][4], al[4][4];
            #pragma unroll
            for (int mi = 0; mi < 4; mi++) {
                uint32_t base = sb + (uint32_t)((mb + mi * 16) * ROWB + ks * 32) + arow;
                ldsm4(ah[mi], base + AHI_OFF);
                ldsm4(al[mi], base + ALO_OFF);
            }
            #pragma unroll
            for (int ni = 0; ni < 4; ni++) {
                uint32_t base = sb + (uint32_t)((nb + ni * 8) * ROWB + ks * 32) + brow;
                uint32_t bh[2], bl[2];
                ldsm2(bh, base + BHI_OFF);
                ldsm2(bl, base + BLO_OFF);
                #pragma unroll
                for (int mi = 0; mi < 4; mi++) mma16816(acc[mi][ni], ah[mi], bh);
                #pragma unroll
                for (int mi = 0; mi < 4; mi++) mma16816(acc[mi][ni], ah[mi], bl);
                #pragma unroll
                for (int mi = 0; mi < 4; mi++) mma16816(acc[mi][ni], al[mi], bh);
            }
        }
        asm volatile("cp.async.wait_group 0;" ::: "memory");
        __syncthreads();
    }

    int r0 = lane >> 2, c2 = (lane & 3) * 2;
    #pragma unroll
    for (int mi = 0; mi < 4; mi++) {
        int rowa = m0 + mb + mi * 16 + r0;
        #pragma unroll
        for (int ni = 0; ni < 4; ni++) {
            int col = n0 + nb + ni * 8 + c2;
            *(float2*)(C + (size_t)rowa * N + col) = make_float2(acc[mi][ni][0], acc[mi][ni][1]);
            *(float2*)(C + (size_t)(rowa + 8) * N + col) = make_float2(acc[mi][ni][2], acc[mi][ni][3]);
        }
    }
}

// ---------------- RMSNorm + RoPE + v-mix -> bf16 hi/lo ----------------
__global__ __launch_bounds__(128) void fuse_kernel(
    const float* __restrict__ qkv, const float* __restrict__ ve,
    const float* __restrict__ lambdas,
    __nv_bfloat16* __restrict__ Qh, __nv_bfloat16* __restrict__ Ql,
    __nv_bfloat16* __restrict__ Kh, __nv_bfloat16* __restrict__ Kl,
    __nv_bfloat16* __restrict__ Vh, __nv_bfloat16* __restrict__ Vl)
{
    int t = blockIdx.x, h = blockIdx.y, d = threadIdx.x;
    size_t base = (size_t)t * (3*DIM) + h * HDIM + d;
    float q = qkv[base];
    float k = qkv[base + DIM];
    float v = qkv[base + 2*DIM];

    __shared__ float red[3][4];
    __shared__ float qn_s[128], kn_s[128];
    float sq = q*q, sk = k*k, sv = v*v;
    #pragma unroll
    for (int off = 16; off > 0; off >>= 1) {
        sq += __shfl_xor_sync(0xffffffffu, sq, off);
        sk += __shfl_xor_sync(0xffffffffu, sk, off);
        sv += __shfl_xor_sync(0xffffffffu, sv, off);
    }
    int warp = d >> 5, lane = d & 31;
    if (lane == 0) { red[0][warp] = sq; red[1][warp] = sk; red[2][warp] = sv; }
    __syncthreads();
    sq = red[0][0]+red[0][1]+red[0][2]+red[0][3];
    sk = red[1][0]+red[1][1]+red[1][2]+red[1][3];
    sv = red[2][0]+red[2][1]+red[2][2]+red[2][3];
    float rq = rsqrtf(sq * (1.0f/128.0f) + 1e-6f);
    float rk = rsqrtf(sk * (1.0f/128.0f) + 1e-6f);
    float rv = rsqrtf(sv * (1.0f/128.0f) + 1e-6f);
    float qn = q * rq, kn = k * rk, vn = v * rv;
    qn_s[d] = qn; kn_s[d] = kn;
    __syncthreads();

    int j = (d < 64) ? d : (d - 64);
    float f = (j < 32) ? exp2f(-10.0f * (float)j / 31.0f) : 0.0f;
    float th = (float)t * f;
    float sn, cs;
    sincosf(th, &sn, &cs);
    float oq, ok;
    if (d < 64) {
        oq =  qn * cs + qn_s[d+64] * sn;
        ok =  kn * cs + kn_s[d+64] * sn;
    } else {
        oq = -qn_s[d-64] * sn + qn * cs;
        ok = -kn_s[d-64] * sn + kn * cs;
    }
    float l0 = lambdas[0], l1 = lambdas[1];
    float vm = l0 * vn + l1 * ve[(size_t)t * DIM + h * HDIM + d];

    size_t oidx = ((size_t)h * T_LEN + t) * HDIM + d;
    float oqs = oq * ATTN_SCALE;
    __nv_bfloat16 qhh = __float2bfloat16(oqs);
    __nv_bfloat16 khh = __float2bfloat16(ok);
    __nv_bfloat16 vhh = __float2bfloat16(vm);
    Qh[oidx] = qhh; Ql[oidx] = __float2bfloat16(oqs - __bfloat162float(qhh));
    Kh[oidx] = khh; Kl[oidx] = __float2bfloat16(ok - __bfloat162float(khh));
    Vh[oidx] = vhh; Vl[oidx] = __float2bfloat16(vm - __bfloat162float(vhh));
}

// ---------------- bf16x3 HMMA causal flash attention ----------------
#define AT_ROWB 272
#define QS_HI 0
#define QS_LO 34816
#define KV_BASE 69632
#define ST_KHI 0
#define ST_KLO 17408
#define ST_VHI 34816
#define ST_VLO 52224
#define ST_BYTES 69632
#define ATTN_SMEM (KV_BASE + 2 * ST_BYTES)

__global__ __launch_bounds__(256, 1) void attn_mma(
    const __nv_bfloat16* __restrict__ Qh, const __nv_bfloat16* __restrict__ Ql,
    const __nv_bfloat16* __restrict__ Kh, const __nv_bfloat16* __restrict__ Kl,
    const __nv_bfloat16* __restrict__ Vh, const __nv_bfloat16* __restrict__ Vl,
    __nv_bfloat16* __restrict__ Yh, __nv_bfloat16* __restrict__ Yl)
{
    extern __shared__ char smc[];
    uint32_t sb = smem_to_u32(smc);
    int tid = threadIdx.x, w = tid >> 5, lane = tid & 31;
    int qt = 15 - (int)blockIdx.x;
    int h = blockIdx.y;
    int q0 = qt * 128, nkt = 2 * qt + 2;
    int g = lane >> 2;
    size_t hb = (size_t)h * T_LEN * HDIM;

    {
        const __nv_bfloat16* qsrc = Qh + hb + (size_t)q0 * HDIM;
        const __nv_bfloat16* lsrc = Ql + hb + (size_t)q0 * HDIM;
        #pragma unroll
        for (int rep = 0; rep < 8; rep++) {
            int i = tid + rep * 256;
            int row = i >> 4, ch = i & 15;
            uint32_t d = (uint32_t)(row * AT_ROWB + ch * 16);
            cp16(sb + QS_HI + d, qsrc + row * HDIM + ch * 8);
            cp16(sb + QS_LO + d, lsrc + row * HDIM + ch * 8);
        }
    }
    auto fillKV = [&](int s, int kt) {
        uint32_t b = sb + KV_BASE + s * ST_BYTES;
        size_t base = hb + (size_t)kt * 64 * HDIM;
        #pragma unroll
        for (int rep = 0; rep < 4; rep++) {
            int i = tid + rep * 256;
            int row = i >> 4, ch = i & 15;
            uint32_t d = (uint32_t)(row * AT_ROWB + ch * 16);
            size_t so = base + row * HDIM + ch * 8;
            cp16(b + ST_KHI + d, Kh + so);
            cp16(b + ST_KLO + d, Kl + so);
            cp16(b + ST_VHI + d, Vh + so);
            cp16(b + ST_VLO + d, Vl + so);
        }
    };
    fillKV(0, 0);
    asm volatile("cp.async.commit_group;" ::: "memory");

    float o[16][4];
    #pragma unroll
    for (int jn = 0; jn < 16; jn++)
        #pragma unroll
        for (int u = 0; u < 4; u++) o[jn][u] = 0.0f;
    float m0 = -1e30f, m1 = -1e30f, l0 = 0.0f, l1 = 0.0f;

    for (int kt = 0; kt < nkt; kt++) {
        asm volatile("cp.async.wait_group 0;" ::: "memory");
        __syncthreads();
        if (kt + 1 < nkt) {
            fillKV((kt + 1) & 1, kt + 1);
            asm volatile("cp.async.commit_group;" ::: "memory");
        }
        if (kt * 64 > q0 + w * 16 + 15) continue;
        uint32_t kvs = sb + KV_BASE + (kt & 1) * ST_BYTES;

        float c[8][4];
        #pragma unroll
        for (int jn = 0; jn < 8; jn++)
            #pragma unroll
            for (int u = 0; u < 4; u++) c[jn][u] = 0.0f;

        {
            uint32_t qh[4], ql_[4], bh[2], bl[2];
            #pragma unroll 2
            for (int ks = 0; ks < 8; ks++) {
                uint32_t qa = sb + (uint32_t)((w * 16 + (lane & 15)) * AT_ROWB + ks * 32 + (lane >> 4) * 16);
                ldsm4(qh, qa + QS_HI);
                ldsm4(ql_, qa + QS_LO);
                #pragma unroll
                for (int jn = 0; jn < 8; jn++) {
                    uint32_t ka = kvs + (uint32_t)((jn * 8 + (lane & 7)) * AT_ROWB + ks * 32 + ((lane >> 3) & 1) * 16);
                    ldsm2(bh, ka + ST_KHI);
                    ldsm2(bl, ka + ST_KLO);
                    mma16816(c[jn], qh, bh);
                    mma16816(c[jn], qh, bl);
                    mma16816(c[jn], ql_, bh);
                }
            }
        }

        if (kt * 64 + 63 > q0 + w * 16) {
            int r0 = q0 + w * 16 + g;
            #pragma unroll
            for (int jn = 0; jn < 8; jn++) {
                int cb = kt * 64 + jn * 8 + (lane & 3) * 2;
                if (cb     > r0)     c[jn][0] = -1e30f;
                if (cb + 1 > r0)     c[jn][1] = -1e30f;
                if (cb     > r0 + 8) c[jn][2] = -1e30f;
                if (cb + 1 > r0 + 8) c[jn][3] = -1e30f;
            }
        }

        float mx0 = -1e30f, mx1 = -1e30f;
        #pragma unroll
        for (int jn = 0; jn < 8; jn++) {
            mx0 = fmaxf(mx0, fmaxf(c[jn][0], c[jn][1]));
            mx1 = fmaxf(mx1, fmaxf(c[jn][2], c[jn][3]));
        }
        mx0 = fmaxf(mx0, __shfl_xor_sync(0xffffffffu, mx0, 1));
        mx0 = fmaxf(mx0, __shfl_xor_sync(0xffffffffu, mx0, 2));
        mx1 = fmaxf(mx1, __shfl_xor_sync(0xffffffffu, mx1, 1));
        mx1 = fmaxf(mx1, __shfl_xor_sync(0xffffffffu, mx1, 2));
        float mn0 = fmaxf(m0, mx0), mn1 = fmaxf(m1, mx1);
        float a0 = fexp(m0 - mn0), a1 = fexp(m1 - mn1);
        m0 = mn0; m1 = mn1;
        l0 *= a0; l1 *= a1;
        #pragma unroll
        for (int jn = 0; jn < 16; jn++) {
            o[jn][0] *= a0; o[jn][1] *= a0;
            o[jn][2] *= a1; o[jn][3] *= a1;
        }
        float rs0 = 0.0f, rs1 = 0.0f;
        #pragma unroll
        for (int jn = 0; jn < 8; jn++) {
            c[jn][0] = fexp(c[jn][0] - mn0);
            c[jn][1] = fexp(c[jn][1] - mn0);
            c[jn][2] = fexp(c[jn][2] - mn1);
            c[jn][3] = fexp(c[jn][3] - mn1);
            rs0 += c[jn][0] + c[jn][1];
            rs1 += c[jn][2] + c[jn][3];
        }
        rs0 += __shfl_xor_sync(0xffffffffu, rs0, 1);
        rs0 += __shfl_xor_sync(0xffffffffu, rs0, 2);
        rs1 += __shfl_xor_sync(0xffffffffu, rs1, 1);
        rs1 += __shfl_xor_sync(0xffffffffu, rs1, 2);
        l0 += rs0; l1 += rs1;

        #pragma unroll
        for (int kk = 0; kk < 4; kk++) {
            uint32_t ah[4], al[4];
            #pragma unroll
            for (int half = 0; half < 2; half++) {
                int t2 = 2 * kk + half;
                __nv_bfloat162 h01 = __floats2bfloat162_rn(c[t2][0], c[t2][1]);
                __nv_bfloat162 h23 = __floats2bfloat162_rn(c[t2][2], c[t2][3]);
                __nv_bfloat162 L01 = __floats2bfloat162_rn(
                    c[t2][0] - __bfloat162float(h01.x), c[t2][1] - __bfloat162float(h01.y));
                __nv_bfloat162 L23 = __floats2bfloat162_rn(
                    c[t2][2] - __bfloat162float(h23.x), c[t2][3] - __bfloat162float(h23.y));
                ah[half * 2 + 0] = *(uint32_t*)&h01;
                ah[half * 2 + 1] = *(uint32_t*)&h23;
                al[half * 2 + 0] = *(uint32_t*)&L01;
                al[half * 2 + 1] = *(uint32_t*)&L23;
            }
            uint32_t af_h[4] = {ah[0], ah[1], ah[2], ah[3]};
            uint32_t af_l[4] = {al[0], al[1], al[2], al[3]};
            uint32_t bh[2], bl[2];
            #pragma unroll
            for (int jn = 0; jn < 16; jn++) {
                uint32_t va = kvs + (uint32_t)((kk * 16 + (lane & 15)) * AT_ROWB + jn * 16);
                ldsm2t(bh, va + ST_VHI);
                ldsm2t(bl, va + ST_VLO);
                mma16816(o[jn], af_h, bh);
                mma16816(o[jn], af_h, bl);
                mma16816(o[jn], af_l, bh);
            }
        }
    }

    float inv0 = 1.0f / l0, inv1 = 1.0f / l1;
    int r0 = q0 + w * 16 + g;
    #pragma unroll
    for (int jn = 0; jn < 16; jn++) {
        int col = h * HDIM + jn * 8 + (lane & 3) * 2;
        float v0 = o[jn][0] * inv0, v1 = o[jn][1] * inv0;
        float v2 = o[jn][2] * inv1, v3 = o[jn][3] * inv1;
        __nv_bfloat162 h01 = __floats2bfloat162_rn(v0, v1);
        __nv_bfloat162 L01 = __floats2bfloat162_rn(v0 - __bfloat162float(h01.x),
                                                   v1 - __bfloat162float(h01.y));
        __nv_bfloat162 h23 = __floats2bfloat162_rn(v2, v3);
        __nv_bfloat162 L23 = __floats2bfloat162_rn(v2 - __bfloat162float(h23.x),
                                                   v3 - __bfloat162float(h23.y));
        *(__nv_bfloat162*)(Yh + (size_t)r0 * DIM + col) = h01;
        *(__nv_bfloat162*)(Yl + (size_t)r0 * DIM + col) = L01;
        *(__nv_bfloat162*)(Yh + (size_t)(r0 + 8) * DIM + col) = h23;
        *(__nv_bfloat162*)(Yl + (size_t)(r0 + 8) * DIM + col) = L23;
    }
}

// ---------------- launch ----------------
extern "C" void kernel_launch(void* const* d_in, const int* in_sizes, int n_in,
                              void* d_out, int out_size)
{
    const float* x       = (const float*)d_in[0];
    const float* w       = (const float*)d_in[1];   // [4,2048,2048]
    const float* ve      = (const float*)d_in[2];
    const float* lambdas = (const float*)d_in[3];
    float* out = (float*)d_out;

    float *p_qkv;
    __nv_bfloat16 *p_whi, *p_wlo, *p_xhi, *p_xlo, *p_yhi, *p_ylo;
    __nv_bfloat16 *p_qh, *p_ql, *p_kh, *p_kl, *p_vh, *p_vl;
    cudaGetSymbolAddress((void**)&p_qkv, g_qkv);
    cudaGetSymbolAddress((void**)&p_whi, g_whi);
    cudaGetSymbolAddress((void**)&p_wlo, g_wlo);
    cudaGetSymbolAddress((void**)&p_xhi, g_xhi);
    cudaGetSymbolAddress((void**)&p_xlo, g_xlo);
    cudaGetSymbolAddress((void**)&p_yhi, g_yhi);
    cudaGetSymbolAddress((void**)&p_ylo, g_ylo);
    cudaGetSymbolAddress((void**)&p_qh, g_qh);
    cudaGetSymbolAddress((void**)&p_ql, g_ql);
    cudaGetSymbolAddress((void**)&p_kh, g_kh);
    cudaGetSymbolAddress((void**)&p_kl, g_kl);
    cudaGetSymbolAddress((void**)&p_vh, g_vh);
    cudaGetSymbolAddress((void**)&p_vl, g_vl);

    cudaFuncSetAttribute(gemm_bf16x3, cudaFuncAttributeMaxDynamicSharedMemorySize, GEMM_SMEM);
    cudaFuncSetAttribute(attn_mma, cudaFuncAttributeMaxDynamicSharedMemorySize, ATTN_SMEM);

    split_kernel<<<(4*DIM*DIM)/1024, 256>>>((const float4*)w, (uint2*)p_whi, (uint2*)p_wlo, 4*DIM*DIM/4);
    split_kernel<<<(T_LEN*DIM)/1024, 256>>>((const float4*)x, (uint2*)p_xhi, (uint2*)p_xlo, T_LEN*DIM/4);

    gemm_bf16x3<<<dim3(3*DIM/128, T_LEN/128), 256, GEMM_SMEM>>>(
        p_xhi, p_xlo, p_whi, p_wlo, p_qkv, T_LEN, 3*DIM, DIM);

    fuse_kernel<<<dim3(T_LEN, NHEAD), 128>>>(p_qkv, ve, lambdas,
        p_qh, p_ql, p_kh, p_kl, p_vh, p_vl);

    attn_mma<<<dim3(16, NHEAD), 256, ATTN_SMEM>>>(
        p_qh, p_ql, p_kh, p_kl, p_vh, p_vl, p_yhi, p_ylo);

    gemm_bf16x3<<<dim3(DIM/128, T_LEN/128), 256, GEMM_SMEM>>>(
        p_yhi, p_ylo, p_whi + (size_t)3*DIM*DIM, p_wlo + (size_t)3*DIM*DIM, out, T_LEN, DIM, DIM);
}

// round 11
// speedup vs baseline: 3.0174x; 1.0017x over previous
#include <cuda_runtime.h>
#include <cuda_bf16.h>
#include <math.h>
#include <stdint.h>

#define DIM 2048
#define T_LEN 2048
#define NHEAD 16
#define HDIM 128
#define ATTN_SCALE 0.12f

// ---------------- scratch ----------------
__device__ float g_qkv[T_LEN * 3 * DIM];
__device__ __nv_bfloat16 g_whi[4 * DIM * DIM];
__device__ __nv_bfloat16 g_wlo[4 * DIM * DIM];
__device__ __nv_bfloat16 g_xhi[T_LEN * DIM];
__device__ __nv_bfloat16 g_xlo[T_LEN * DIM];
__device__ __nv_bfloat16 g_yhi[T_LEN * DIM];
__device__ __nv_bfloat16 g_ylo[T_LEN * DIM];
__device__ __nv_bfloat16 g_qh[NHEAD * T_LEN * HDIM];
__device__ __nv_bfloat16 g_ql[NHEAD * T_LEN * HDIM];
__device__ __nv_bfloat16 g_kh[NHEAD * T_LEN * HDIM];
__device__ __nv_bfloat16 g_kl[NHEAD * T_LEN * HDIM];
__device__ __nv_bfloat16 g_vh[NHEAD * T_LEN * HDIM];
__device__ __nv_bfloat16 g_vl[NHEAD * T_LEN * HDIM];

// ---------------- PTX helpers (portable sm_80+) ----------------
__device__ __forceinline__ uint32_t smem_to_u32(const void* p) {
    uint32_t a;
    asm("{ .reg .u64 t; cvta.to.shared.u64 t, %1; cvt.u32.u64 %0, t; }" : "=r"(a) : "l"(p));
    return a;
}
__device__ __forceinline__ void cp16(uint32_t dst, const void* src) {
    asm volatile("cp.async.cg.shared.global [%0], [%1], 16;" :: "r"(dst), "l"(src) : "memory");
}
__device__ __forceinline__ void ldsm4(uint32_t* r, uint32_t a) {
    asm volatile("ldmatrix.sync.aligned.m8n8.x4.shared.b16 {%0,%1,%2,%3}, [%4];"
        : "=r"(r[0]), "=r"(r[1]), "=r"(r[2]), "=r"(r[3]) : "r"(a));
}
__device__ __forceinline__ void ldsm2(uint32_t* r, uint32_t a) {
    asm volatile("ldmatrix.sync.aligned.m8n8.x2.shared.b16 {%0,%1}, [%2];"
        : "=r"(r[0]), "=r"(r[1]) : "r"(a));
}
__device__ __forceinline__ void ldsm2t(uint32_t* r, uint32_t a) {
    asm volatile("ldmatrix.sync.aligned.m8n8.x2.trans.shared.b16 {%0,%1}, [%2];"
        : "=r"(r[0]), "=r"(r[1]) : "r"(a));
}
__device__ __forceinline__ void mma16816(float* d, const uint32_t* a, const uint32_t* b) {
    asm volatile("mma.sync.aligned.m16n8k16.row.col.f32.bf16.bf16.f32 "
        "{%0,%1,%2,%3}, {%4,%5,%6,%7}, {%8,%9}, {%0,%1,%2,%3};"
        : "+f"(d[0]), "+f"(d[1]), "+f"(d[2]), "+f"(d[3])
        : "r"(a[0]), "r"(a[1]), "r"(a[2]), "r"(a[3]), "r"(b[0]), "r"(b[1]));
}

// fast e^x for x <= 0 (FMA pipe only)
__device__ __forceinline__ float fexp(float x) {
    float t = fmaxf(x * 1.4426950408889634f, -80.0f);
    float z = t + 12582912.0f;
    float f = t - (z - 12582912.0f);
    int  i = __float_as_int(z) - 0x4B400000;
    float p = 1.3333558146e-3f;
    p = fmaf(p, f, 9.6181291076e-3f);
    p = fmaf(p, f, 5.5504108664e-2f);
    p = fmaf(p, f, 2.4022650696e-1f);
    p = fmaf(p, f, 6.9314718056e-1f);
    p = fmaf(p, f, 1.0f);
    return __int_as_float(__float_as_int(p) + (i << 23));
}

// ---------------- fp32 -> bf16 hi/lo split (8 floats/thread, 16B stores) ----------------
__global__ __launch_bounds__(256) void split_kernel(
    const float4* __restrict__ src, uint4* __restrict__ hi, uint4* __restrict__ lo, int n8)
{
    int i = blockIdx.x * 256 + threadIdx.x;
    if (i >= n8) return;
    float4 v0 = src[2 * i];
    float4 v1 = src[2 * i + 1];
    float a[8] = {v0.x, v0.y, v0.z, v0.w, v1.x, v1.y, v1.z, v1.w};
    uint32_t hb[8], lb[8];
    #pragma unroll
    for (int u = 0; u < 8; u++) {
        __nv_bfloat16 h = __float2bfloat16(a[u]);
        float l = a[u] - __bfloat162float(h);
        hb[u] = (uint32_t)__bfloat16_as_ushort(h);
        lb[u] = (uint32_t)__bfloat16_as_ushort(__float2bfloat16(l));
    }
    uint4 H, L;
    H.x = hb[0] | (hb[1] << 16); H.y = hb[2] | (hb[3] << 16);
    H.z = hb[4] | (hb[5] << 16); H.w = hb[6] | (hb[7] << 16);
    L.x = lb[0] | (lb[1] << 16); L.y = lb[2] | (lb[3] << 16);
    L.z = lb[4] | (lb[5] << 16); L.w = lb[6] | (lb[7] << 16);
    hi[i] = H; lo[i] = L;
}

// ---------------- bf16x3 HMMA GEMM: C[M,N] = A[M,K] * B[N,K]^T ----------------
#define GKC 32
#define ROWB 80
#define AHI_OFF 0
#define ALO_OFF 10240
#define BHI_OFF 20480
#define BLO_OFF 30720
#define STAGE_BYTES 40960
#define GEMM_SMEM (2 * STAGE_BYTES)

__global__ __launch_bounds__(256, 2) void gemm_bf16x3(
    const __nv_bfloat16* __restrict__ Ahi, const __nv_bfloat16* __restrict__ Alo,
    const __nv_bfloat16* __restrict__ Bhi, const __nv_bfloat16* __restrict__ Blo,
    float* __restrict__ C, int M, int N, int K)
{
    extern __shared__ char smc[];
    uint32_t smem_base = smem_to_u32(smc);
    int tid = threadIdx.x, wid = tid >> 5, lane = tid & 31;
    int m0 = blockIdx.y * 128, n0 = blockIdx.x * 128;
    int wy = wid & 1, wx = wid >> 1;
    int mb = wy * 64, nb = wx * 32;

    uint32_t arow = (uint32_t)((lane & 15) * ROWB + ((lane >> 4) & 1) * 16);
    // B ldsm4 lane map: 2 ni-blocks (16 N-rows) x 16 k per load
    uint32_t brow4 = (uint32_t)(((lane & 7) + ((lane >> 4) & 1) * 8) * ROWB + ((lane >> 3) & 1) * 16);

    float acc[4][4][4];
    #pragma unroll
    for (int i = 0; i < 4; i++)
        #pragma unroll
        for (int j = 0; j < 4; j++)
            #pragma unroll
            for (int u = 0; u < 4; u++) acc[i][j][u] = 0.0f;

    auto fill_async = [&](int s, int k0) {
        uint32_t sb = smem_base + s * STAGE_BYTES;
        #pragma unroll
        for (int rep = 0; rep < 2; rep++) {
            int i = tid + rep * 256;
            int row = i >> 2, seg = i & 3;
            uint32_t doff = (uint32_t)(row * ROWB + seg * 16);
            size_t ga = (size_t)(m0 + row) * K + k0 + seg * 8;
            size_t gb = (size_t)(n0 + row) * K + k0 + seg * 8;
            cp16(sb + AHI_OFF + doff, Ahi + ga);
            cp16(sb + ALO_OFF + doff, Alo + ga);
            cp16(sb + BHI_OFF + doff, Bhi + gb);
            cp16(sb + BLO_OFF + doff, Blo + gb);
        }
    };

    const int nchunks = K / GKC;
    fill_async(0, 0);
    asm volatile("cp.async.commit_group;" ::: "memory");
    asm volatile("cp.async.wait_group 0;" ::: "memory");
    __syncthreads();

    for (int c = 0; c < nchunks; c++) {
        if (c + 1 < nchunks) fill_async((c + 1) & 1, (c + 1) * GKC);
        asm volatile("cp.async.commit_group;" ::: "memory");

        uint32_t sb = smem_base + (c & 1) * STAGE_BYTES;
        #pragma unroll
        for (int ks = 0; ks < 2; ks++) {
            uint32_t ah[4][4], al[4][4];
            #pragma unroll
            for (int mi = 0; mi < 4; mi++) {
                uint32_t base = sb + (uint32_t)((mb + mi * 16) * ROWB + ks * 32) + arow;
                ldsm4(ah[mi], base + AHI_OFF);
                ldsm4(al[mi], base + ALO_OFF);
            }
            #pragma unroll
            for (int np = 0; np < 2; np++) {     // ni pair: covers ni=2*np, 2*np+1
                uint32_t base = sb + (uint32_t)((nb + np * 16) * ROWB + ks * 32) + brow4;
                uint32_t bh[4], bl[4];
                ldsm4(bh, base + BHI_OFF);
                ldsm4(bl, base + BLO_OFF);
                #pragma unroll
                for (int half = 0; half < 2; half++) {
                    int ni = 2 * np + half;
                    #pragma unroll
                    for (int mi = 0; mi < 4; mi++) mma16816(acc[mi][ni], ah[mi], bh + 2 * half);
                    #pragma unroll
                    for (int mi = 0; mi < 4; mi++) mma16816(acc[mi][ni], ah[mi], bl + 2 * half);
                    #pragma unroll
                    for (int mi = 0; mi < 4; mi++) mma16816(acc[mi][ni], al[mi], bh + 2 * half);
                }
            }
        }
        asm volatile("cp.async.wait_group 0;" ::: "memory");
        __syncthreads();
    }

    int r0 = lane >> 2, c2 = (lane & 3) * 2;
    #pragma unroll
    for (int mi = 0; mi < 4; mi++) {
        int rowa = m0 + mb + mi * 16 + r0;
        #pragma unroll
        for (int ni = 0; ni < 4; ni++) {
            int col = n0 + nb + ni * 8 + c2;
            *(float2*)(C + (size_t)rowa * N + col) = make_float2(acc[mi][ni][0], acc[mi][ni][1]);
            *(float2*)(C + (size_t)(rowa + 8) * N + col) = make_float2(acc[mi][ni][2], acc[mi][ni][3]);
        }
    }
}

// ---------------- RMSNorm + RoPE + v-mix -> bf16 hi/lo ----------------
__global__ __launch_bounds__(128) void fuse_kernel(
    const float* __restrict__ qkv, const float* __restrict__ ve,
    const float* __restrict__ lambdas,
    __nv_bfloat16* __restrict__ Qh, __nv_bfloat16* __restrict__ Ql,
    __nv_bfloat16* __restrict__ Kh, __nv_bfloat16* __restrict__ Kl,
    __nv_bfloat16* __restrict__ Vh, __nv_bfloat16* __restrict__ Vl)
{
    int t = blockIdx.x, h = blockIdx.y, d = threadIdx.x;
    size_t base = (size_t)t * (3*DIM) + h * HDIM + d;
    float q = qkv[base];
    float k = qkv[base + DIM];
    float v = qkv[base + 2*DIM];

    __shared__ float red[3][4];
    __shared__ float qn_s[128], kn_s[128];
    float sq = q*q, sk = k*k, sv = v*v;
    #pragma unroll
    for (int off = 16; off > 0; off >>= 1) {
        sq += __shfl_xor_sync(0xffffffffu, sq, off);
        sk += __shfl_xor_sync(0xffffffffu, sk, off);
        sv += __shfl_xor_sync(0xffffffffu, sv, off);
    }
    int warp = d >> 5, lane = d & 31;
    if (lane == 0) { red[0][warp] = sq; red[1][warp] = sk; red[2][warp] = sv; }
    __syncthreads();
    sq = red[0][0]+red[0][1]+red[0][2]+red[0][3];
    sk = red[1][0]+red[1][1]+red[1][2]+red[1][3];
    sv = red[2][0]+red[2][1]+red[2][2]+red[2][3];
    float rq = rsqrtf(sq * (1.0f/128.0f) + 1e-6f);
    float rk = rsqrtf(sk * (1.0f/128.0f) + 1e-6f);
    float rv = rsqrtf(sv * (1.0f/128.0f) + 1e-6f);
    float qn = q * rq, kn = k * rk, vn = v * rv;
    qn_s[d] = qn; kn_s[d] = kn;
    __syncthreads();

    int j = (d < 64) ? d : (d - 64);
    float f = (j < 32) ? exp2f(-10.0f * (float)j / 31.0f) : 0.0f;
    float th = (float)t * f;
    float sn, cs;
    sincosf(th, &sn, &cs);
    float oq, ok;
    if (d < 64) {
        oq =  qn * cs + qn_s[d+64] * sn;
        ok =  kn * cs + kn_s[d+64] * sn;
    } else {
        oq = -qn_s[d-64] * sn + qn * cs;
        ok = -kn_s[d-64] * sn + kn * cs;
    }
    float l0 = lambdas[0], l1 = lambdas[1];
    float vm = l0 * vn + l1 * ve[(size_t)t * DIM + h * HDIM + d];

    size_t oidx = ((size_t)h * T_LEN + t) * HDIM + d;
    float oqs = oq * ATTN_SCALE;
    __nv_bfloat16 qhh = __float2bfloat16(oqs);
    __nv_bfloat16 khh = __float2bfloat16(ok);
    __nv_bfloat16 vhh = __float2bfloat16(vm);
    Qh[oidx] = qhh; Ql[oidx] = __float2bfloat16(oqs - __bfloat162float(qhh));
    Kh[oidx] = khh; Kl[oidx] = __float2bfloat16(ok - __bfloat162float(khh));
    Vh[oidx] = vhh; Vl[oidx] = __float2bfloat16(vm - __bfloat162float(vhh));
}

// ---------------- bf16x3 HMMA causal flash attention ----------------
#define AT_ROWB 272
#define QS_HI 0
#define QS_LO 34816
#define KV_BASE 69632
#define ST_KHI 0
#define ST_KLO 17408
#define ST_VHI 34816
#define ST_VLO 52224
#define ST_BYTES 69632
#define ATTN_SMEM (KV_BASE + 2 * ST_BYTES)

__global__ __launch_bounds__(256, 1) void attn_mma(
    const __nv_bfloat16* __restrict__ Qh, const __nv_bfloat16* __restrict__ Ql,
    const __nv_bfloat16* __restrict__ Kh, const __nv_bfloat16* __restrict__ Kl,
    const __nv_bfloat16* __restrict__ Vh, const __nv_bfloat16* __restrict__ Vl,
    __nv_bfloat16* __restrict__ Yh, __nv_bfloat16* __restrict__ Yl)
{
    extern __shared__ char smc[];
    uint32_t sb = smem_to_u32(smc);
    int tid = threadIdx.x, w = tid >> 5, lane = tid & 31;
    int qt = 15 - (int)blockIdx.x;
    int h = blockIdx.y;
    int q0 = qt * 128, nkt = 2 * qt + 2;
    int g = lane >> 2;
    size_t hb = (size_t)h * T_LEN * HDIM;

    {
        const __nv_bfloat16* qsrc = Qh + hb + (size_t)q0 * HDIM;
        const __nv_bfloat16* lsrc = Ql + hb + (size_t)q0 * HDIM;
        #pragma unroll
        for (int rep = 0; rep < 8; rep++) {
            int i = tid + rep * 256;
            int row = i >> 4, ch = i & 15;
            uint32_t d = (uint32_t)(row * AT_ROWB + ch * 16);
            cp16(sb + QS_HI + d, qsrc + row * HDIM + ch * 8);
            cp16(sb + QS_LO + d, lsrc + row * HDIM + ch * 8);
        }
    }
    auto fillKV = [&](int s, int kt) {
        uint32_t b = sb + KV_BASE + s * ST_BYTES;
        size_t base = hb + (size_t)kt * 64 * HDIM;
        #pragma unroll
        for (int rep = 0; rep < 4; rep++) {
            int i = tid + rep * 256;
            int row = i >> 4, ch = i & 15;
            uint32_t d = (uint32_t)(row * AT_ROWB + ch * 16);
            size_t so = base + row * HDIM + ch * 8;
            cp16(b + ST_KHI + d, Kh + so);
            cp16(b + ST_KLO + d, Kl + so);
            cp16(b + ST_VHI + d, Vh + so);
            cp16(b + ST_VLO + d, Vl + so);
        }
    };
    fillKV(0, 0);
    asm volatile("cp.async.commit_group;" ::: "memory");

    float o[16][4];
    #pragma unroll
    for (int jn = 0; jn < 16; jn++)
        #pragma unroll
        for (int u = 0; u < 4; u++) o[jn][u] = 0.0f;
    float m0 = -1e30f, m1 = -1e30f, l0 = 0.0f, l1 = 0.0f;

    for (int kt = 0; kt < nkt; kt++) {
        asm volatile("cp.async.wait_group 0;" ::: "memory");
        __syncthreads();
        if (kt + 1 < nkt) {
            fillKV((kt + 1) & 1, kt + 1);
            asm volatile("cp.async.commit_group;" ::: "memory");
        }
        if (kt * 64 > q0 + w * 16 + 15) continue;
        uint32_t kvs = sb + KV_BASE + (kt & 1) * ST_BYTES;

        float c[8][4];
        #pragma unroll
        for (int jn = 0; jn < 8; jn++)
            #pragma unroll
            for (int u = 0; u < 4; u++) c[jn][u] = 0.0f;

        {
            uint32_t qh[4], ql_[4], bh[2], bl[2];
            #pragma unroll 2
            for (int ks = 0; ks < 8; ks++) {
                uint32_t qa = sb + (uint32_t)((w * 16 + (lane & 15)) * AT_ROWB + ks * 32 + (lane >> 4) * 16);
                ldsm4(qh, qa + QS_HI);
                ldsm4(ql_, qa + QS_LO);
                #pragma unroll
                for (int jn = 0; jn < 8; jn++) {
                    uint32_t ka = kvs + (uint32_t)((jn * 8 + (lane & 7)) * AT_ROWB + ks * 32 + ((lane >> 3) & 1) * 16);
                    ldsm2(bh, ka + ST_KHI);
                    ldsm2(bl, ka + ST_KLO);
                    mma16816(c[jn], qh, bh);
                    mma16816(c[jn], qh, bl);
                    mma16816(c[jn], ql_, bh);
                }
            }
        }

        if (kt * 64 + 63 > q0 + w * 16) {
            int r0 = q0 + w * 16 + g;
            #pragma unroll
            for (int jn = 0; jn < 8; jn++) {
                int cb = kt * 64 + jn * 8 + (lane & 3) * 2;
                if (cb     > r0)     c[jn][0] = -1e30f;
                if (cb + 1 > r0)     c[jn][1] = -1e30f;
                if (cb     > r0 + 8) c[jn][2] = -1e30f;
                if (cb + 1 > r0 + 8) c[jn][3] = -1e30f;
            }
        }

        float mx0 = -1e30f, mx1 = -1e30f;
        #pragma unroll
        for (int jn = 0; jn < 8; jn++) {
            mx0 = fmaxf(mx0, fmaxf(c[jn][0], c[jn][1]));
            mx1 = fmaxf(mx1, fmaxf(c[jn][2], c[jn][3]));
        }
        mx0 = fmaxf(mx0, __shfl_xor_sync(0xffffffffu, mx0, 1));
        mx0 = fmaxf(mx0, __shfl_xor_sync(0xffffffffu, mx0, 2));
        mx1 = fmaxf(mx1, __shfl_xor_sync(0xffffffffu, mx1, 1));
        mx1 = fmaxf(mx1, __shfl_xor_sync(0xffffffffu, mx1, 2));
        float mn0 = fmaxf(m0, mx0), mn1 = fmaxf(m1, mx1);
        float a0 = fexp(m0 - mn0), a1 = fexp(m1 - mn1);
        m0 = mn0; m1 = mn1;
        l0 *= a0; l1 *= a1;
        #pragma unroll
        for (int jn = 0; jn < 16; jn++) {
            o[jn][0] *= a0; o[jn][1] *= a0;
            o[jn][2] *= a1; o[jn][3] *= a1;
        }
        float rs0 = 0.0f, rs1 = 0.0f;
        #pragma unroll
        for (int jn = 0; jn < 8; jn++) {
            c[jn][0] = fexp(c[jn][0] - mn0);
            c[jn][1] = fexp(c[jn][1] - mn0);
            c[jn][2] = fexp(c[jn][2] - mn1);
            c[jn][3] = fexp(c[jn][3] - mn1);
            rs0 += c[jn][0] + c[jn][1];
            rs1 += c[jn][2] + c[jn][3];
        }
        rs0 += __shfl_xor_sync(0xffffffffu, rs0, 1);
        rs0 += __shfl_xor_sync(0xffffffffu, rs0, 2);
        rs1 += __shfl_xor_sync(0xffffffffu, rs1, 1);
        rs1 += __shfl_xor_sync(0xffffffffu, rs1, 2);
        l0 += rs0; l1 += rs1;

        #pragma unroll
        for (int kk = 0; kk < 4; kk++) {
            uint32_t ah[4], al[4];
            #pragma unroll
            for (int half = 0; half < 2; half++) {
                int t2 = 2 * kk + half;
                __nv_bfloat162 h01 = __floats2bfloat162_rn(c[t2][0], c[t2][1]);
                __nv_bfloat162 h23 = __floats2bfloat162_rn(c[t2][2], c[t2][3]);
                __nv_bfloat162 L01 = __floats2bfloat162_rn(
                    c[t2][0] - __bfloat162float(h01.x), c[t2][1] - __bfloat162float(h01.y));
                __nv_bfloat162 L23 = __floats2bfloat162_rn(
                    c[t2][2] - __bfloat162float(h23.x), c[t2][3] - __bfloat162float(h23.y));
                ah[half * 2 + 0] = *(uint32_t*)&h01;
                ah[half * 2 + 1] = *(uint32_t*)&h23;
                al[half * 2 + 0] = *(uint32_t*)&L01;
                al[half * 2 + 1] = *(uint32_t*)&L23;
            }
            uint32_t af_h[4] = {ah[0], ah[1], ah[2], ah[3]};
            uint32_t af_l[4] = {al[0], al[1], al[2], al[3]};
            uint32_t bh[2], bl[2];
            #pragma unroll
            for (int jn = 0; jn < 16; jn++) {
                uint32_t va = kvs + (uint32_t)((kk * 16 + (lane & 15)) * AT_ROWB + jn * 16);
                ldsm2t(bh, va + ST_VHI);
                ldsm2t(bl, va + ST_VLO);
                mma16816(o[jn], af_h, bh);
                mma16816(o[jn], af_h, bl);
                mma16816(o[jn], af_l, bh);
            }
        }
    }

    float inv0 = 1.0f / l0, inv1 = 1.0f / l1;
    int r0 = q0 + w * 16 + g;
    #pragma unroll
    for (int jn = 0; jn < 16; jn++) {
        int col = h * HDIM + jn * 8 + (lane & 3) * 2;
        float v0 = o[jn][0] * inv0, v1 = o[jn][1] * inv0;
        float v2 = o[jn][2] * inv1, v3 = o[jn][3] * inv1;
        __nv_bfloat162 h01 = __floats2bfloat162_rn(v0, v1);
        __nv_bfloat162 L01 = __floats2bfloat162_rn(v0 - __bfloat162float(h01.x),
                                                   v1 - __bfloat162float(h01.y));
        __nv_bfloat162 h23 = __floats2bfloat162_rn(v2, v3);
        __nv_bfloat162 L23 = __floats2bfloat162_rn(v2 - __bfloat162float(h23.x),
                                                   v3 - __bfloat162float(h23.y));
        *(__nv_bfloat162*)(Yh + (size_t)r0 * DIM + col) = h01;
        *(__nv_bfloat162*)(Yl + (size_t)r0 * DIM + col) = L01;
        *(__nv_bfloat162*)(Yh + (size_t)(r0 + 8) * DIM + col) = h23;
        *(__nv_bfloat162*)(Yl + (size_t)(r0 + 8) * DIM + col) = L23;
    }
}

// ---------------- launch ----------------
extern "C" void kernel_launch(void* const* d_in, const int* in_sizes, int n_in,
                              void* d_out, int out_size)
{
    const float* x       = (const float*)d_in[0];
    const float* w       = (const float*)d_in[1];
    const float* ve      = (const float*)d_in[2];
    const float* lambdas = (const float*)d_in[3];
    float* out = (float*)d_out;

    float *p_qkv;
    __nv_bfloat16 *p_whi, *p_wlo, *p_xhi, *p_xlo, *p_yhi, *p_ylo;
    __nv_bfloat16 *p_qh, *p_ql, *p_kh, *p_kl, *p_vh, *p_vl;
    cudaGetSymbolAddress((void**)&p_qkv, g_qkv);
    cudaGetSymbolAddress((void**)&p_whi, g_whi);
    cudaGetSymbolAddress((void**)&p_wlo, g_wlo);
    cudaGetSymbolAddress((void**)&p_xhi, g_xhi);
    cudaGetSymbolAddress((void**)&p_xlo, g_xlo);
    cudaGetSymbolAddress((void**)&p_yhi, g_yhi);
    cudaGetSymbolAddress((void**)&p_ylo, g_ylo);
    cudaGetSymbolAddress((void**)&p_qh, g_qh);
    cudaGetSymbolAddress((void**)&p_ql, g_ql);
    cudaGetSymbolAddress((void**)&p_kh, g_kh);
    cudaGetSymbolAddress((void**)&p_kl, g_kl);
    cudaGetSymbolAddress((void**)&p_vh, g_vh);
    cudaGetSymbolAddress((void**)&p_vl, g_vl);

    cudaFuncSetAttribute(gemm_bf16x3, cudaFuncAttributeMaxDynamicSharedMemorySize, GEMM_SMEM);
    cudaFuncSetAttribute(attn_mma, cudaFuncAttributeMaxDynamicSharedMemorySize, ATTN_SMEM);

    split_kernel<<<(4*DIM*DIM)/2048, 256>>>((const float4*)w, (uint4*)p_whi, (uint4*)p_wlo, 4*DIM*DIM/8);
    split_kernel<<<(T_LEN*DIM)/2048, 256>>>((const float4*)x, (uint4*)p_xhi, (uint4*)p_xlo, T_LEN*DIM/8);

    gemm_bf16x3<<<dim3(3*DIM/128, T_LEN/128), 256, GEMM_SMEM>>>(
        p_xhi, p_xlo, p_whi, p_wlo, p_qkv, T_LEN, 3*DIM, DIM);

    fuse_kernel<<<dim3(T_LEN, NHEAD), 128>>>(p_qkv, ve, lambdas,
        p_qh, p_ql, p_kh, p_kl, p_vh, p_vl);

    attn_mma<<<dim3(16, NHEAD), 256, ATTN_SMEM>>>(
        p_qh, p_ql, p_kh, p_kl, p_vh, p_vl, p_yhi, p_ylo);

    gemm_bf16x3<<<dim3(DIM/128, T_LEN/128), 256, GEMM_SMEM>>>(
        p_yhi, p_ylo, p_whi + (size_t)3*DIM*DIM, p_wlo + (size_t)3*DIM*DIM, out, T_LEN, DIM, DIM);
}